// round 3
// baseline (speedup 1.0000x reference)
#include <cuda_runtime.h>
#include <math.h>

// ---------------- compile-time problem shape ----------------
#define TT 4096    // B*S tokens
#define DD 1024
#define HH 2048
#define OO 1024
#define EE 8
#define MAXTILES 72            // max sum over experts of ceil(cnt_e/128)  (proven <= 71)
#define BUFROWS (MAXTILES*128) // 9216

// ---------------- scratch (device globals; no allocation allowed) ----------------
__device__ float g_xn  [(size_t)TT*DD];       // LN1 output
__device__ float g_h1  [(size_t)TT*HH];       // shared expert hidden
__device__ float g_sh  [(size_t)TT*OO];       // shared expert output
__device__ float g_hid2[(size_t)BUFROWS*HH];  // expert hidden (compacted rows)
__device__ float g_eout2[(size_t)BUFROWS*OO]; // expert output (compacted rows)
__device__ int   g_tki [TT*2];
__device__ float g_tkw [TT*2];
__device__ int   g_rank[TT*2];
__device__ int   g_perm[BUFROWS];
__device__ int   g_counts[EE];
__device__ int   g_cursor[EE];
__device__ int   g_base[EE];
__device__ int   g_tile_expert[MAXTILES];
__device__ int   g_tile_rows[MAXTILES];

__device__ __forceinline__ float gelu_exact(float x) {
    return 0.5f * x * (1.0f + erff(x * 0.70710678118654752440f));
}

// block-wide 2-value sum reduce; blockDim.x == 256; sh must have >= 16 floats
__device__ __forceinline__ void block_reduce2(float& s, float& s2, float* sh) {
    #pragma unroll
    for (int o = 16; o; o >>= 1) {
        s  += __shfl_down_sync(0xffffffffu, s,  o);
        s2 += __shfl_down_sync(0xffffffffu, s2, o);
    }
    int w = threadIdx.x >> 5, l = threadIdx.x & 31;
    if (l == 0) { sh[w] = s; sh[8 + w] = s2; }
    __syncthreads();
    if (threadIdx.x == 0) {
        float a = 0.f, b = 0.f;
        #pragma unroll
        for (int i = 0; i < 8; i++) { a += sh[i]; b += sh[8 + i]; }
        sh[0] = a; sh[8] = b;
    }
    __syncthreads();
    s = sh[0]; s2 = sh[8];
}

// ---------------- LN1 (one block / token) + reset counters ----------------
__global__ void ln1_kernel(const float* __restrict__ x,
                           const float* __restrict__ g,
                           const float* __restrict__ b) {
    int t = blockIdx.x, tid = threadIdx.x;
    if (t == 0 && tid < EE) g_counts[tid] = 0;  // consumed only by later kernels
    const float* xr = x + (size_t)t * DD;
    float v[4], s = 0.f, s2 = 0.f;
    #pragma unroll
    for (int i = 0; i < 4; i++) {
        v[i] = xr[tid + i * 256];
        s += v[i]; s2 += v[i] * v[i];
    }
    __shared__ float sh[16];
    block_reduce2(s, s2, sh);
    float m   = s  * (1.0f / DD);
    float var = s2 * (1.0f / DD) - m * m;
    float inv = rsqrtf(var + 1e-5f);
    float* yr = g_xn + (size_t)t * DD;
    #pragma unroll
    for (int i = 0; i < 4; i++) {
        int d = tid + i * 256;
        yr[d] = (v[i] - m) * inv * g[d] + b[d];
    }
}

// ---------------- router: logits, softmax, top-2, counts (one block / token) ----------------
__global__ void router_kernel(const float* __restrict__ rw,
                              const float* __restrict__ rb) {
    int t = blockIdx.x, tid = threadIdx.x;
    const float* xr = g_xn + (size_t)t * DD;
    float p[EE];
    #pragma unroll
    for (int e = 0; e < EE; e++) p[e] = 0.f;
    for (int d = tid; d < DD; d += 256) {
        float xv = xr[d];
        #pragma unroll
        for (int e = 0; e < EE; e++) p[e] += xv * rw[e * DD + d];
    }
    __shared__ float s[256][EE];
    #pragma unroll
    for (int e = 0; e < EE; e++) s[tid][e] = p[e];
    __syncthreads();
    for (int o = 128; o; o >>= 1) {
        if (tid < o) {
            #pragma unroll
            for (int e = 0; e < EE; e++) s[tid][e] += s[tid + o][e];
        }
        __syncthreads();
    }
    if (tid == 0) {
        float l[EE];
        #pragma unroll
        for (int e = 0; e < EE; e++) l[e] = s[0][e] + rb[e];
        int i0 = 0;
        #pragma unroll
        for (int e = 1; e < EE; e++) if (l[e] > l[i0]) i0 = e;   // first max wins ties
        int i1 = (i0 == 0) ? 1 : 0;
        #pragma unroll
        for (int e = 0; e < EE; e++) if (e != i0 && l[e] > l[i1]) i1 = e;
        float e0 = 1.0f;                      // exp(l[i0]-l[i0])
        float e1 = expf(l[i1] - l[i0]);
        float inv = 1.0f / (e0 + e1);
        g_tki[2 * t] = i0;  g_tki[2 * t + 1] = i1;
        g_tkw[2 * t] = e0 * inv;  g_tkw[2 * t + 1] = e1 * inv;
        atomicAdd(&g_counts[i0], 1);
        atomicAdd(&g_counts[i1], 1);
    }
}

// ---------------- segment prefix (single thread; E=8 trivial) ----------------
__global__ void prefix_kernel() {
    int rowbase = 0, tile = 0;
    for (int e = 0; e < EE; e++) {
        int cnt = g_counts[e];
        g_base[e] = rowbase;
        g_cursor[e] = 0;
        int nt = (cnt + 127) >> 7;
        for (int j = 0; j < nt; j++) {
            g_tile_expert[tile] = e;
            int rem = cnt - j * 128;
            g_tile_rows[tile] = rem < 128 ? rem : 128;
            tile++;
        }
        rowbase += nt << 7;
    }
    for (; tile < MAXTILES; tile++) { g_tile_expert[tile] = -1; g_tile_rows[tile] = 0; }
}

// ---------------- placement: compact assignment list ----------------
__global__ void place_kernel() {
    int i = blockIdx.x * blockDim.x + threadIdx.x;   // 0..2T-1
    if (i >= TT * 2) return;
    int e = g_tki[i];
    int pos = g_base[e] + atomicAdd(&g_cursor[e], 1);
    g_perm[pos] = i >> 1;
    g_rank[i] = pos;
}

// ---------------- tiled SGEMM: C[M,N] = A[M,K] * B[N,K]^T + bias (opt. GELU) ----------------
// MODE 0: plain rows (shared expert).  MODE 1: A rows gathered via g_perm (expert GEMM1).
// MODE 2: A rows compact/direct, B selected per tile's expert (expert GEMM2).
template <int MODE, bool GELU>
__global__ __launch_bounds__(256)
void gemm_kernel(const float* __restrict__ A, const float* __restrict__ Bw,
                 const float* __restrict__ bias, float* __restrict__ C,
                 int N, int Kd) {
    constexpr int BM = 128, BN = 128, BK = 16;
    int tileM = blockIdx.y, tileN = blockIdx.x;
    int valid = BM;
    const float* Bp = Bw;
    const float* bp = bias;
    if (MODE != 0) {
        int e = g_tile_expert[tileM];
        if (e < 0) return;
        valid = g_tile_rows[tileM];
        if (MODE == 1) { Bp = Bw + (size_t)e * HH * DD; bp = bias + e * HH; }
        else           { Bp = Bw + (size_t)e * OO * HH; bp = bias + e * OO; }
    }
    int row0 = tileM * BM, col0 = tileN * BN;
    int tid = threadIdx.x;
    int lr = tid >> 2;            // 0..63
    int lk = (tid & 3) * 4;       // 0,4,8,12

    int i0 = lr, i1 = lr + 64;
    const float* a0p = nullptr;
    const float* a1p = nullptr;
    if (MODE == 1) {
        if (i0 < valid) a0p = A + (size_t)g_perm[row0 + i0] * Kd;
        if (i1 < valid) a1p = A + (size_t)g_perm[row0 + i1] * Kd;
    } else {
        a0p = A + (size_t)(row0 + i0) * Kd;
        a1p = A + (size_t)(row0 + i1) * Kd;
    }
    const float* b0p = Bp + (size_t)(col0 + lr) * Kd;
    const float* b1p = Bp + (size_t)(col0 + lr + 64) * Kd;

    __shared__ float As[BK][BM];
    __shared__ float Bs[BK][BN];
    float acc[8][8];
    #pragma unroll
    for (int i = 0; i < 8; i++)
        #pragma unroll
        for (int j = 0; j < 8; j++) acc[i][j] = 0.f;

    int ty = tid >> 4, tx = tid & 15;

    for (int kt = 0; kt < Kd; kt += BK) {
        float4 a0 = a0p ? *(const float4*)(a0p + kt + lk) : make_float4(0.f, 0.f, 0.f, 0.f);
        float4 a1 = a1p ? *(const float4*)(a1p + kt + lk) : make_float4(0.f, 0.f, 0.f, 0.f);
        float4 b0 = *(const float4*)(b0p + kt + lk);
        float4 b1 = *(const float4*)(b1p + kt + lk);
        As[lk + 0][i0] = a0.x; As[lk + 1][i0] = a0.y; As[lk + 2][i0] = a0.z; As[lk + 3][i0] = a0.w;
        As[lk + 0][i1] = a1.x; As[lk + 1][i1] = a1.y; As[lk + 2][i1] = a1.z; As[lk + 3][i1] = a1.w;
        Bs[lk + 0][lr]      = b0.x; Bs[lk + 1][lr]      = b0.y; Bs[lk + 2][lr]      = b0.z; Bs[lk + 3][lr]      = b0.w;
        Bs[lk + 0][lr + 64] = b1.x; Bs[lk + 1][lr + 64] = b1.y; Bs[lk + 2][lr + 64] = b1.z; Bs[lk + 3][lr + 64] = b1.w;
        __syncthreads();
        #pragma unroll
        for (int kk = 0; kk < BK; kk++) {
            float4 av0 = *(const float4*)&As[kk][ty * 8];
            float4 av1 = *(const float4*)&As[kk][ty * 8 + 4];
            float4 bv0 = *(const float4*)&Bs[kk][tx * 8];
            float4 bv1 = *(const float4*)&Bs[kk][tx * 8 + 4];
            float av[8] = {av0.x, av0.y, av0.z, av0.w, av1.x, av1.y, av1.z, av1.w};
            float bv[8] = {bv0.x, bv0.y, bv0.z, bv0.w, bv1.x, bv1.y, bv1.z, bv1.w};
            #pragma unroll
            for (int ii = 0; ii < 8; ii++)
                #pragma unroll
                for (int jj = 0; jj < 8; jj++)
                    acc[ii][jj] += av[ii] * bv[jj];
        }
        __syncthreads();
    }

    #pragma unroll
    for (int ii = 0; ii < 8; ii++) {
        int i = ty * 8 + ii;
        if (MODE != 0 && i >= valid) continue;
        size_t crow = (size_t)(row0 + i) * N + col0;
        #pragma unroll
        for (int jj = 0; jj < 8; jj++) {
            int n = tx * 8 + jj;
            float vv = acc[ii][jj] + bp[col0 + n];
            if (GELU) vv = gelu_exact(vv);
            C[crow + n] = vv;
        }
    }
}

// ---------------- combine (shared/9 + top-2 mix) + LN2, one block / token ----------------
__global__ void combine_kernel(const float* __restrict__ g2,
                               const float* __restrict__ b2,
                               float* __restrict__ out) {
    int t = blockIdx.x, tid = threadIdx.x;
    int r0 = g_rank[2 * t], r1 = g_rank[2 * t + 1];
    float w0 = g_tkw[2 * t], w1 = g_tkw[2 * t + 1];
    const float* sh = g_sh + (size_t)t * OO;
    const float* e0 = g_eout2 + (size_t)r0 * OO;
    const float* e1 = g_eout2 + (size_t)r1 * OO;
    float v[4], s = 0.f, s2 = 0.f;
    #pragma unroll
    for (int i = 0; i < 4; i++) {
        int o = tid + i * 256;
        v[i] = sh[o] * (1.0f / 9.0f) + w0 * e0[o] + w1 * e1[o];
        s += v[i]; s2 += v[i] * v[i];
    }
    __shared__ float shm[16];
    block_reduce2(s, s2, shm);
    float m   = s  * (1.0f / OO);
    float var = s2 * (1.0f / OO) - m * m;
    float inv = rsqrtf(var + 1e-5f);
    float* orow = out + (size_t)t * OO;
    #pragma unroll
    for (int i = 0; i < 4; i++) {
        int o = tid + i * 256;
        orow[o] = (v[i] - m) * inv * g2[o] + b2[o];
    }
}

// ---------------- launch ----------------
extern "C" void kernel_launch(void* const* d_in, const int* in_sizes, int n_in,
                              void* d_out, int out_size) {
    const float* x        = (const float*)d_in[0];
    const float* ln1_g    = (const float*)d_in[1];
    const float* ln1_b    = (const float*)d_in[2];
    const float* router_w = (const float*)d_in[3];
    const float* router_b = (const float*)d_in[4];
    const float* sh_w1    = (const float*)d_in[5];
    const float* sh_b1    = (const float*)d_in[6];
    const float* sh_w2    = (const float*)d_in[7];
    const float* sh_b2    = (const float*)d_in[8];
    const float* e_w1     = (const float*)d_in[9];
    const float* e_b1     = (const float*)d_in[10];
    const float* e_w2     = (const float*)d_in[11];
    const float* e_b2     = (const float*)d_in[12];
    const float* ln2_g    = (const float*)d_in[13];
    const float* ln2_b    = (const float*)d_in[14];
    float* out = (float*)d_out;

    float *p_xn, *p_h1, *p_sh, *p_hid2, *p_eout2;
    cudaGetSymbolAddress((void**)&p_xn,    g_xn);
    cudaGetSymbolAddress((void**)&p_h1,    g_h1);
    cudaGetSymbolAddress((void**)&p_sh,    g_sh);
    cudaGetSymbolAddress((void**)&p_hid2,  g_hid2);
    cudaGetSymbolAddress((void**)&p_eout2, g_eout2);

    // 1) LN1 (+ counter reset)
    ln1_kernel<<<TT, 256>>>(x, ln1_g, ln1_b);
    // 2) router: top-2 + counts
    router_kernel<<<TT, 256>>>(router_w, router_b);
    // 3) segment layout
    prefix_kernel<<<1, 1>>>();
    // 4) compact placement
    place_kernel<<<(TT * 2) / 256, 256>>>();
    // 5) shared expert GEMM1 (GELU) : [T,H] = xn @ sh_w1^T
    gemm_kernel<0, true ><<<dim3(HH / 128, TT / 128), 256>>>(p_xn, sh_w1, sh_b1, p_h1, HH, DD);
    // 6) shared expert GEMM2        : [T,O] = h1 @ sh_w2^T
    gemm_kernel<0, false><<<dim3(OO / 128, TT / 128), 256>>>(p_h1, sh_w2, sh_b2, p_sh, OO, HH);
    // 7) expert GEMM1 (gathered rows, GELU) : hid2 = xn[perm] @ e_w1[e]^T
    gemm_kernel<1, true ><<<dim3(HH / 128, MAXTILES), 256>>>(p_xn, e_w1, e_b1, p_hid2, HH, DD);
    // 8) expert GEMM2 (compact rows)        : eout2 = hid2 @ e_w2[e]^T
    gemm_kernel<2, false><<<dim3(OO / 128, MAXTILES), 256>>>(p_hid2, e_w2, e_b2, p_eout2, OO, HH);
    // 9) combine + LN2
    combine_kernel<<<TT, 256>>>(ln2_g, ln2_b, out);
}

// round 5
// speedup vs baseline: 2.9381x; 2.9381x over previous
#include <cuda_runtime.h>
#include <math.h>
#include <stdint.h>

// ---------------- compile-time problem shape ----------------
#define TT 4096    // B*S tokens
#define DD 1024
#define HH 2048
#define OO 1024
#define EE 8
#define MAXTILES 72            // max sum over experts of ceil(cnt_e/128)
#define BUFROWS (MAXTILES*128) // 9216

// ---------------- scratch (device globals; no allocation allowed) ----------------
__device__ float g_xn  [(size_t)TT*DD];       // LN1 output (exact fp32, for router)
__device__ float g_xnr [(size_t)TT*DD];       // LN1 output rounded to tf32 (for GEMMs)
__device__ float g_h1  [(size_t)TT*HH];       // shared expert hidden (tf32-rounded)
__device__ float g_sh  [(size_t)TT*OO];       // shared expert output (fp32)
__device__ float g_hid2[(size_t)BUFROWS*HH];  // expert hidden, compact (tf32-rounded)
__device__ float g_eout2[(size_t)BUFROWS*OO]; // expert output, compact (fp32)
// tf32-rounded weight copies
__device__ float g_w1c [(size_t)EE*HH*DD];
__device__ float g_w2c [(size_t)EE*OO*HH];
__device__ float g_sw1 [(size_t)HH*DD];
__device__ float g_sw2 [(size_t)OO*HH];

__device__ int   g_tki [TT*2];
__device__ float g_tkw [TT*2];
__device__ int   g_rank[TT*2];
__device__ int   g_perm[BUFROWS];
__device__ int   g_counts[EE];
__device__ int   g_cursor[EE];
__device__ int   g_base[EE];
__device__ int   g_tile_expert[MAXTILES];
__device__ int   g_tile_rows[MAXTILES];

// ---------------- PTX helpers (baseline features only; legal on compute_103) ----------------
__device__ __forceinline__ uint32_t smem_u32(const void* p) {
    uint32_t a;
    asm("{ .reg .u64 t; cvta.to.shared.u64 t, %1; cvt.u32.u64 %0, t; }" : "=r"(a) : "l"(p));
    return a;
}
__device__ __forceinline__ float round_tf32(float x) {
    uint32_t u;
    asm("cvt.rna.tf32.f32 %0, %1;" : "=r"(u) : "f"(x));
    return __uint_as_float(u);
}
__device__ __forceinline__ void cpa16(uint32_t dst, const void* src) {
    asm volatile("cp.async.cg.shared.global [%0], [%1], 16;" :: "r"(dst), "l"(src));
}
#define CP_COMMIT()  asm volatile("cp.async.commit_group;" ::: "memory")
#define CP_WAIT1()   asm volatile("cp.async.wait_group 1;" ::: "memory")

// mma.sync m16n8k8 tf32: D = A*B + D (f32 accum)
#define MMA_TF32(c, a, b) \
    asm volatile("mma.sync.aligned.m16n8k8.row.col.f32.tf32.tf32.f32 " \
        "{%0,%1,%2,%3}, {%4,%5,%6,%7}, {%8,%9}, {%0,%1,%2,%3};" \
        : "+f"((c)[0]), "+f"((c)[1]), "+f"((c)[2]), "+f"((c)[3]) \
        : "r"((a)[0]), "r"((a)[1]), "r"((a)[2]), "r"((a)[3]), \
          "r"((b)[0]), "r"((b)[1]))

__device__ __forceinline__ float gelu_exact(float x) {
    return 0.5f * x * (1.0f + erff(x * 0.70710678118654752440f));
}

// ---------------- small helper: block reduce of 2 scalars ----------------
__device__ __forceinline__ void block_reduce2(float& s, float& s2, float* sh) {
    #pragma unroll
    for (int o = 16; o; o >>= 1) {
        s  += __shfl_down_sync(0xffffffffu, s,  o);
        s2 += __shfl_down_sync(0xffffffffu, s2, o);
    }
    int w = threadIdx.x >> 5, l = threadIdx.x & 31;
    if (l == 0) { sh[w] = s; sh[8 + w] = s2; }
    __syncthreads();
    if (threadIdx.x == 0) {
        float a = 0.f, b = 0.f;
        #pragma unroll
        for (int i = 0; i < 8; i++) { a += sh[i]; b += sh[8 + i]; }
        sh[0] = a; sh[8] = b;
    }
    __syncthreads();
    s = sh[0]; s2 = sh[8];
}

// ---------------- tf32 rounding pass for weights ----------------
__global__ void cvt_tf32_kernel(const float4* __restrict__ src, float4* __restrict__ dst, int n4) {
    int i = blockIdx.x * blockDim.x + threadIdx.x;
    if (i < n4) {
        float4 v = src[i];
        v.x = round_tf32(v.x); v.y = round_tf32(v.y);
        v.z = round_tf32(v.z); v.w = round_tf32(v.w);
        dst[i] = v;
    }
}

// ---------------- LN1 (one block / token) + reset counters ----------------
__global__ void ln1_kernel(const float* __restrict__ x,
                           const float* __restrict__ g,
                           const float* __restrict__ b) {
    int t = blockIdx.x, tid = threadIdx.x;
    if (t == 0 && tid < EE) g_counts[tid] = 0;
    const float* xr = x + (size_t)t * DD;
    float v[4], s = 0.f, s2 = 0.f;
    #pragma unroll
    for (int i = 0; i < 4; i++) {
        v[i] = xr[tid + i * 256];
        s += v[i]; s2 += v[i] * v[i];
    }
    __shared__ float sh[16];
    block_reduce2(s, s2, sh);
    float m   = s  * (1.0f / DD);
    float var = s2 * (1.0f / DD) - m * m;
    float inv = rsqrtf(var + 1e-5f);
    float* yr  = g_xn  + (size_t)t * DD;
    float* yr2 = g_xnr + (size_t)t * DD;
    #pragma unroll
    for (int i = 0; i < 4; i++) {
        int d = tid + i * 256;
        float y = (v[i] - m) * inv * g[d] + b[d];
        yr[d]  = y;
        yr2[d] = round_tf32(y);
    }
}

// ---------------- router (exact fp32 on g_xn) ----------------
__global__ void router_kernel(const float* __restrict__ rw,
                              const float* __restrict__ rb) {
    int t = blockIdx.x, tid = threadIdx.x;
    const float* xr = g_xn + (size_t)t * DD;
    float p[EE];
    #pragma unroll
    for (int e = 0; e < EE; e++) p[e] = 0.f;
    for (int d = tid; d < DD; d += 256) {
        float xv = xr[d];
        #pragma unroll
        for (int e = 0; e < EE; e++) p[e] += xv * rw[e * DD + d];
    }
    __shared__ float s[256][EE];
    #pragma unroll
    for (int e = 0; e < EE; e++) s[tid][e] = p[e];
    __syncthreads();
    for (int o = 128; o; o >>= 1) {
        if (tid < o) {
            #pragma unroll
            for (int e = 0; e < EE; e++) s[tid][e] += s[tid + o][e];
        }
        __syncthreads();
    }
    if (tid == 0) {
        float l[EE];
        #pragma unroll
        for (int e = 0; e < EE; e++) l[e] = s[0][e] + rb[e];
        int i0 = 0;
        #pragma unroll
        for (int e = 1; e < EE; e++) if (l[e] > l[i0]) i0 = e;
        int i1 = (i0 == 0) ? 1 : 0;
        #pragma unroll
        for (int e = 0; e < EE; e++) if (e != i0 && l[e] > l[i1]) i1 = e;
        float e1 = expf(l[i1] - l[i0]);
        float inv = 1.0f / (1.0f + e1);
        g_tki[2 * t] = i0;  g_tki[2 * t + 1] = i1;
        g_tkw[2 * t] = inv; g_tkw[2 * t + 1] = e1 * inv;
        atomicAdd(&g_counts[i0], 1);
        atomicAdd(&g_counts[i1], 1);
    }
}

// ---------------- segment prefix ----------------
__global__ void prefix_kernel() {
    int rowbase = 0, tile = 0;
    for (int e = 0; e < EE; e++) {
        int cnt = g_counts[e];
        g_base[e] = rowbase;
        g_cursor[e] = 0;
        int nt = (cnt + 127) >> 7;
        for (int j = 0; j < nt; j++) {
            g_tile_expert[tile] = e;
            int rem = cnt - j * 128;
            g_tile_rows[tile] = rem < 128 ? rem : 128;
            tile++;
        }
        rowbase += nt << 7;
    }
    for (; tile < MAXTILES; tile++) { g_tile_expert[tile] = -1; g_tile_rows[tile] = 0; }
}

// ---------------- placement ----------------
__global__ void place_kernel() {
    int i = blockIdx.x * blockDim.x + threadIdx.x;
    if (i >= TT * 2) return;
    int e = g_tki[i];
    int pos = g_base[e] + atomicAdd(&g_cursor[e], 1);
    g_perm[pos] = i >> 1;
    g_rank[i] = pos;
}

// ============ tf32 mma.sync GEMM: C[M,N] = A[M,K] @ B[N,K]^T + bias ============
// BM=128, BN=128, BK=32, 256 threads (8 warps: 4 in M x 2 in N), warp tile 32x64.
// Double-buffered cp.async.  Smem rows padded to 36 floats (conflict-free frag LDS).
// MODE 0: plain A rows.  MODE 1: A rows gathered via g_perm, B/bias per expert (w1).
// MODE 2: A compact rows, B/bias per expert (w2).  GELU => output rounded to tf32.
#define BKF 32
#define ROWP 36                       // padded row length in floats
#define STAGE_BYTES (128 * ROWP * 4)  // 18432
#define SM_A 0
#define SM_B (2 * STAGE_BYTES)        // 36864
#define GEMM_SMEM (4 * STAGE_BYTES)   // 73728

template <int MODE, bool GELU>
__global__ __launch_bounds__(256)
void mma_gemm(const float* __restrict__ A, const float* __restrict__ Bw,
              const float* __restrict__ bias, float* __restrict__ C,
              int N, int Kd) {
    int tileM = blockIdx.y, tileN = blockIdx.x;
    int valid = 128;
    const float* Bp = Bw;
    const float* bp = bias;
    if (MODE != 0) {
        int e = g_tile_expert[tileM];
        if (e < 0) return;
        valid = g_tile_rows[tileM];
        if (MODE == 1) { Bp = Bw + (size_t)e * HH * DD; bp = bias + (size_t)e * HH; }
        else           { Bp = Bw + (size_t)e * OO * HH; bp = bias + (size_t)e * OO; }
    }
    int row0 = tileM * 128, col0 = tileN * 128;
    int tid = threadIdx.x;
    int wid = tid >> 5, lane = tid & 31;
    int gid = lane >> 2, tig = lane & 3;
    int warpM = wid & 3, warpN = wid >> 2;

    extern __shared__ char smem[];
    uint32_t sb = smem_u32(smem);

    // ---- loader mapping: thread handles rows lm+32*i (i=0..3), 4 floats at lk ----
    int lm = tid >> 3;          // 0..31
    int lk = (tid & 7) * 4;     // 0,4,...,28
    const float* aPtr[4];
    const float* bPtr[4];
    #pragma unroll
    for (int i = 0; i < 4; i++) {
        int m = lm + 32 * i;
        if (MODE == 1) {
            int mc = (m < valid) ? m : (valid - 1);
            aPtr[i] = A + (size_t)g_perm[row0 + mc] * Kd;
        } else {
            aPtr[i] = A + (size_t)(row0 + m) * Kd;
        }
        bPtr[i] = Bp + (size_t)(col0 + m) * Kd;
    }

    auto load_stage = [&](int kt, int buf) {
        uint32_t aB = sb + SM_A + buf * STAGE_BYTES;
        uint32_t bB = sb + SM_B + buf * STAGE_BYTES;
        #pragma unroll
        for (int i = 0; i < 4; i++) {
            uint32_t off = ((lm + 32 * i) * ROWP + lk) * 4;
            cpa16(aB + off, aPtr[i] + kt + lk);
            cpa16(bB + off, bPtr[i] + kt + lk);
        }
        CP_COMMIT();
    };

    float acc[2][8][4];
    #pragma unroll
    for (int mi = 0; mi < 2; mi++)
        #pragma unroll
        for (int nj = 0; nj < 8; nj++)
            #pragma unroll
            for (int q = 0; q < 4; q++) acc[mi][nj][q] = 0.f;

    int NK = Kd / BKF;
    load_stage(0, 0);

    for (int kt = 0; kt < NK; kt++) {
        int buf = kt & 1;
        if (kt + 1 < NK) load_stage((kt + 1) * BKF, (kt + 1) & 1);
        else CP_COMMIT();
        CP_WAIT1();
        __syncthreads();

        const float* As = (const float*)(smem + SM_A + buf * STAGE_BYTES);
        const float* Bs = (const float*)(smem + SM_B + buf * STAGE_BYTES);
        #pragma unroll
        for (int k8 = 0; k8 < BKF; k8 += 8) {
            uint32_t af[2][4], bf[8][2];
            #pragma unroll
            for (int mi = 0; mi < 2; mi++) {
                int m = warpM * 32 + mi * 16 + gid;
                af[mi][0] = __float_as_uint(As[m * ROWP + k8 + tig]);
                af[mi][1] = __float_as_uint(As[(m + 8) * ROWP + k8 + tig]);
                af[mi][2] = __float_as_uint(As[m * ROWP + k8 + tig + 4]);
                af[mi][3] = __float_as_uint(As[(m + 8) * ROWP + k8 + tig + 4]);
            }
            #pragma unroll
            for (int nj = 0; nj < 8; nj++) {
                int n = warpN * 64 + nj * 8 + gid;
                bf[nj][0] = __float_as_uint(Bs[n * ROWP + k8 + tig]);
                bf[nj][1] = __float_as_uint(Bs[n * ROWP + k8 + tig + 4]);
            }
            #pragma unroll
            for (int mi = 0; mi < 2; mi++)
                #pragma unroll
                for (int nj = 0; nj < 8; nj++)
                    MMA_TF32(acc[mi][nj], af[mi], bf[nj]);
        }
        __syncthreads();
    }

    // ---- epilogue: bias (+ GELU + tf32 round), direct global stores ----
    #pragma unroll
    for (int mi = 0; mi < 2; mi++) {
        int li0 = warpM * 32 + mi * 16 + gid;   // local row of c0/c1
        int li1 = li0 + 8;                       // local row of c2/c3
        bool ok0 = (MODE == 0) || (li0 < valid);
        bool ok1 = (MODE == 0) || (li1 < valid);
        float* c0row = C + (size_t)(row0 + li0) * N + col0;
        float* c1row = C + (size_t)(row0 + li1) * N + col0;
        #pragma unroll
        for (int nj = 0; nj < 8; nj++) {
            int c = warpN * 64 + nj * 8 + tig * 2;
            float b0 = bp[col0 + c], b1 = bp[col0 + c + 1];
            float v0 = acc[mi][nj][0] + b0;
            float v1 = acc[mi][nj][1] + b1;
            float v2 = acc[mi][nj][2] + b0;
            float v3 = acc[mi][nj][3] + b1;
            if (GELU) {
                v0 = round_tf32(gelu_exact(v0));
                v1 = round_tf32(gelu_exact(v1));
                v2 = round_tf32(gelu_exact(v2));
                v3 = round_tf32(gelu_exact(v3));
            }
            if (ok0) *(float2*)(c0row + c) = make_float2(v0, v1);
            if (ok1) *(float2*)(c1row + c) = make_float2(v2, v3);
        }
    }
}

// ---------------- combine + LN2 ----------------
__global__ void combine_kernel(const float* __restrict__ g2,
                               const float* __restrict__ b2,
                               float* __restrict__ out) {
    int t = blockIdx.x, tid = threadIdx.x;
    int r0 = g_rank[2 * t], r1 = g_rank[2 * t + 1];
    float w0 = g_tkw[2 * t], w1 = g_tkw[2 * t + 1];
    const float* sh = g_sh + (size_t)t * OO;
    const float* e0 = g_eout2 + (size_t)r0 * OO;
    const float* e1 = g_eout2 + (size_t)r1 * OO;
    float v[4], s = 0.f, s2 = 0.f;
    #pragma unroll
    for (int i = 0; i < 4; i++) {
        int o = tid + i * 256;
        v[i] = sh[o] * (1.0f / 9.0f) + w0 * e0[o] + w1 * e1[o];
        s += v[i]; s2 += v[i] * v[i];
    }
    __shared__ float shm[16];
    block_reduce2(s, s2, shm);
    float m   = s  * (1.0f / OO);
    float var = s2 * (1.0f / OO) - m * m;
    float inv = rsqrtf(var + 1e-5f);
    float* orow = out + (size_t)t * OO;
    #pragma unroll
    for (int i = 0; i < 4; i++) {
        int o = tid + i * 256;
        orow[o] = (v[i] - m) * inv * g2[o] + b2[o];
    }
}

// ---------------- launch ----------------
extern "C" void kernel_launch(void* const* d_in, const int* in_sizes, int n_in,
                              void* d_out, int out_size) {
    const float* x        = (const float*)d_in[0];
    const float* ln1_g    = (const float*)d_in[1];
    const float* ln1_b    = (const float*)d_in[2];
    const float* router_w = (const float*)d_in[3];
    const float* router_b = (const float*)d_in[4];
    const float* sh_w1    = (const float*)d_in[5];
    const float* sh_b1    = (const float*)d_in[6];
    const float* sh_w2    = (const float*)d_in[7];
    const float* sh_b2    = (const float*)d_in[8];
    const float* e_w1     = (const float*)d_in[9];
    const float* e_b1     = (const float*)d_in[10];
    const float* e_w2     = (const float*)d_in[11];
    const float* e_b2     = (const float*)d_in[12];
    const float* ln2_g    = (const float*)d_in[13];
    const float* ln2_b    = (const float*)d_in[14];
    float* out = (float*)d_out;

    float *p_xnr, *p_h1, *p_sh, *p_hid2, *p_eout2, *p_w1c, *p_w2c, *p_sw1, *p_sw2;
    cudaGetSymbolAddress((void**)&p_xnr,   g_xnr);
    cudaGetSymbolAddress((void**)&p_h1,    g_h1);
    cudaGetSymbolAddress((void**)&p_sh,    g_sh);
    cudaGetSymbolAddress((void**)&p_hid2,  g_hid2);
    cudaGetSymbolAddress((void**)&p_eout2, g_eout2);
    cudaGetSymbolAddress((void**)&p_w1c,   g_w1c);
    cudaGetSymbolAddress((void**)&p_w2c,   g_w2c);
    cudaGetSymbolAddress((void**)&p_sw1,   g_sw1);
    cudaGetSymbolAddress((void**)&p_sw2,   g_sw2);

    cudaFuncSetAttribute(mma_gemm<0, true >, cudaFuncAttributeMaxDynamicSharedMemorySize, GEMM_SMEM);
    cudaFuncSetAttribute(mma_gemm<0, false>, cudaFuncAttributeMaxDynamicSharedMemorySize, GEMM_SMEM);
    cudaFuncSetAttribute(mma_gemm<1, true >, cudaFuncAttributeMaxDynamicSharedMemorySize, GEMM_SMEM);
    cudaFuncSetAttribute(mma_gemm<2, false>, cudaFuncAttributeMaxDynamicSharedMemorySize, GEMM_SMEM);

    // weight rounding passes (tf32 rna)
    {
        int n4;
        n4 = EE * HH * DD / 4; cvt_tf32_kernel<<<n4 / 256, 256>>>((const float4*)e_w1, (float4*)p_w1c, n4);
        n4 = EE * OO * HH / 4; cvt_tf32_kernel<<<n4 / 256, 256>>>((const float4*)e_w2, (float4*)p_w2c, n4);
        n4 = HH * DD / 4;      cvt_tf32_kernel<<<n4 / 256, 256>>>((const float4*)sh_w1, (float4*)p_sw1, n4);
        n4 = OO * HH / 4;      cvt_tf32_kernel<<<n4 / 256, 256>>>((const float4*)sh_w2, (float4*)p_sw2, n4);
    }

    ln1_kernel<<<TT, 256>>>(x, ln1_g, ln1_b);
    router_kernel<<<TT, 256>>>(router_w, router_b);
    prefix_kernel<<<1, 1>>>();
    place_kernel<<<(TT * 2) / 256, 256>>>();

    // shared GEMM1 (GELU): [T,H] = xnr @ sw1^T
    mma_gemm<0, true ><<<dim3(HH / 128, TT / 128), 256, GEMM_SMEM>>>(p_xnr, p_sw1, sh_b1, p_h1, HH, DD);
    // shared GEMM2: [T,O] = h1 @ sw2^T
    mma_gemm<0, false><<<dim3(OO / 128, TT / 128), 256, GEMM_SMEM>>>(p_h1, p_sw2, sh_b2, p_sh, OO, HH);
    // expert GEMM1 (gathered, GELU): hid2 = xnr[perm] @ w1c[e]^T
    mma_gemm<1, true ><<<dim3(HH / 128, MAXTILES), 256, GEMM_SMEM>>>(p_xnr, p_w1c, e_b1, p_hid2, HH, DD);
    // expert GEMM2: eout2 = hid2 @ w2c[e]^T
    mma_gemm<2, false><<<dim3(OO / 128, MAXTILES), 256, GEMM_SMEM>>>(p_hid2, p_w2c, e_b2, p_eout2, OO, HH);

    combine_kernel<<<TT, 256>>>(ln2_g, ln2_b, out);
}

// round 6
// speedup vs baseline: 4.2506x; 1.4467x over previous
#include <cuda_runtime.h>
#include <cuda_fp16.h>
#include <math.h>
#include <stdint.h>

// ---------------- compile-time problem shape ----------------
#define TT 4096    // B*S tokens
#define DD 1024
#define HH 2048
#define OO 1024
#define EE 8
#define MAXTILES 72
#define BUFROWS (MAXTILES*128)

// ---------------- scratch (device globals) ----------------
__device__ __half g_xh  [(size_t)TT*DD];       // LN1 output (fp16, GEMM A operand)
__device__ __half g_h1h [(size_t)TT*HH];       // shared expert hidden (fp16)
__device__ float  g_sh  [(size_t)TT*OO];       // shared expert output (fp32)
__device__ __half g_hid2h[(size_t)BUFROWS*HH]; // expert hidden, compact (fp16)
__device__ float  g_eout2[(size_t)BUFROWS*OO]; // expert output, compact (fp32)
// fp16 weight copies
__device__ __half g_w1h [(size_t)EE*HH*DD];
__device__ __half g_w2h [(size_t)EE*OO*HH];
__device__ __half g_sw1h[(size_t)HH*DD];
__device__ __half g_sw2h[(size_t)OO*HH];

__device__ int   g_tki [TT*2];
__device__ float g_tkw [TT*2];
__device__ int   g_rank[TT*2];
__device__ int   g_perm[BUFROWS];
__device__ int   g_counts[EE];
__device__ int   g_cursor[EE];
__device__ int   g_base[EE];
__device__ int   g_tile_expert[MAXTILES];
__device__ int   g_tile_rows[MAXTILES];

// ---------------- PTX helpers (baseline features; legal on compute_103) ----------------
__device__ __forceinline__ uint32_t smem_u32(const void* p) {
    uint32_t a;
    asm("{ .reg .u64 t; cvta.to.shared.u64 t, %1; cvt.u32.u64 %0, t; }" : "=r"(a) : "l"(p));
    return a;
}
__device__ __forceinline__ void cpa16(uint32_t dst, const void* src) {
    asm volatile("cp.async.cg.shared.global [%0], [%1], 16;" :: "r"(dst), "l"(src));
}
#define CP_COMMIT()  asm volatile("cp.async.commit_group;" ::: "memory")
#define CP_WAIT1()   asm volatile("cp.async.wait_group 1;" ::: "memory")

// mma.sync m16n8k16 fp16 -> fp32 accum
#define MMA_F16(c, a, b) \
    asm volatile("mma.sync.aligned.m16n8k16.row.col.f32.f16.f16.f32 " \
        "{%0,%1,%2,%3}, {%4,%5,%6,%7}, {%8,%9}, {%0,%1,%2,%3};" \
        : "+f"((c)[0]), "+f"((c)[1]), "+f"((c)[2]), "+f"((c)[3]) \
        : "r"((a)[0]), "r"((a)[1]), "r"((a)[2]), "r"((a)[3]), \
          "r"((b)[0]), "r"((b)[1]))

__device__ __forceinline__ float gelu_exact(float x) {
    return 0.5f * x * (1.0f + erff(x * 0.70710678118654752440f));
}

__device__ __forceinline__ void block_reduce2(float& s, float& s2, float* sh) {
    #pragma unroll
    for (int o = 16; o; o >>= 1) {
        s  += __shfl_down_sync(0xffffffffu, s,  o);
        s2 += __shfl_down_sync(0xffffffffu, s2, o);
    }
    int w = threadIdx.x >> 5, l = threadIdx.x & 31;
    if (l == 0) { sh[w] = s; sh[8 + w] = s2; }
    __syncthreads();
    if (threadIdx.x == 0) {
        float a = 0.f, b = 0.f;
        #pragma unroll
        for (int i = 0; i < 8; i++) { a += sh[i]; b += sh[8 + i]; }
        sh[0] = a; sh[8] = b;
    }
    __syncthreads();
    s = sh[0]; s2 = sh[8];
}

// ---------------- fp32 -> fp16 weight convert (+ counter reset, runs pre-router) ----------------
__global__ void cvt_f2h_kernel(const float4* __restrict__ src, uint4* __restrict__ dst, int n8) {
    if (blockIdx.x == 0 && threadIdx.x < EE) g_counts[threadIdx.x] = 0;
    int i = blockIdx.x * blockDim.x + threadIdx.x;
    if (i < n8) {
        float4 v0 = src[2 * i], v1 = src[2 * i + 1];
        __half2 h0 = __floats2half2_rn(v0.x, v0.y);
        __half2 h1 = __floats2half2_rn(v0.z, v0.w);
        __half2 h2 = __floats2half2_rn(v1.x, v1.y);
        __half2 h3 = __floats2half2_rn(v1.z, v1.w);
        uint4 w;
        w.x = *(uint32_t*)&h0; w.y = *(uint32_t*)&h1;
        w.z = *(uint32_t*)&h2; w.w = *(uint32_t*)&h3;
        dst[i] = w;
    }
}

// ---------------- fused LN1 + router (one block / token) ----------------
// LN in exact fp32 (registers), router logits from exact values, output stored fp16.
__global__ void ln1_router_kernel(const float* __restrict__ x,
                                  const float* __restrict__ g,
                                  const float* __restrict__ b,
                                  const float* __restrict__ rw,
                                  const float* __restrict__ rb) {
    int t = blockIdx.x, tid = threadIdx.x;
    const float* xr = x + (size_t)t * DD;
    float v[4], s = 0.f, s2 = 0.f;
    #pragma unroll
    for (int i = 0; i < 4; i++) {
        v[i] = xr[tid + i * 256];
        s += v[i]; s2 += v[i] * v[i];
    }
    __shared__ float sh[16];
    block_reduce2(s, s2, sh);
    float m   = s  * (1.0f / DD);
    float var = s2 * (1.0f / DD) - m * m;
    float inv = rsqrtf(var + 1e-5f);

    __half* yr = g_xh + (size_t)t * DD;
    float p[EE];
    #pragma unroll
    for (int e = 0; e < EE; e++) p[e] = 0.f;
    #pragma unroll
    for (int i = 0; i < 4; i++) {
        int d = tid + i * 256;
        float y = (v[i] - m) * inv * g[d] + b[d];
        yr[d] = __float2half_rn(y);
        #pragma unroll
        for (int e = 0; e < EE; e++) p[e] += y * rw[e * DD + d];
    }
    __shared__ float sl[256][EE];
    #pragma unroll
    for (int e = 0; e < EE; e++) sl[tid][e] = p[e];
    __syncthreads();
    for (int o = 128; o; o >>= 1) {
        if (tid < o) {
            #pragma unroll
            for (int e = 0; e < EE; e++) sl[tid][e] += sl[tid + o][e];
        }
        __syncthreads();
    }
    if (tid == 0) {
        float l[EE];
        #pragma unroll
        for (int e = 0; e < EE; e++) l[e] = sl[0][e] + rb[e];
        int i0 = 0;
        #pragma unroll
        for (int e = 1; e < EE; e++) if (l[e] > l[i0]) i0 = e;
        int i1 = (i0 == 0) ? 1 : 0;
        #pragma unroll
        for (int e = 0; e < EE; e++) if (e != i0 && l[e] > l[i1]) i1 = e;
        float e1 = expf(l[i1] - l[i0]);
        float invp = 1.0f / (1.0f + e1);
        g_tki[2 * t] = i0;  g_tki[2 * t + 1] = i1;
        g_tkw[2 * t] = invp; g_tkw[2 * t + 1] = e1 * invp;
        atomicAdd(&g_counts[i0], 1);
        atomicAdd(&g_counts[i1], 1);
    }
}

// ---------------- segment prefix ----------------
__global__ void prefix_kernel() {
    int rowbase = 0, tile = 0;
    for (int e = 0; e < EE; e++) {
        int cnt = g_counts[e];
        g_base[e] = rowbase;
        g_cursor[e] = 0;
        int nt = (cnt + 127) >> 7;
        for (int j = 0; j < nt; j++) {
            g_tile_expert[tile] = e;
            int rem = cnt - j * 128;
            g_tile_rows[tile] = rem < 128 ? rem : 128;
            tile++;
        }
        rowbase += nt << 7;
    }
    for (; tile < MAXTILES; tile++) { g_tile_expert[tile] = -1; g_tile_rows[tile] = 0; }
}

// ---------------- placement ----------------
__global__ void place_kernel() {
    int i = blockIdx.x * blockDim.x + threadIdx.x;
    if (i >= TT * 2) return;
    int e = g_tki[i];
    int pos = g_base[e] + atomicAdd(&g_cursor[e], 1);
    g_perm[pos] = i >> 1;
    g_rank[i] = pos;
}

// ============ fp16 mma.sync GEMM: C[M,N] = A[M,K] @ B[N,K]^T + bias ============
// BM=128, BN=128, BK=64 halves (128B rows), 256 threads (8 warps 4Mx2N), warp tile 32x64.
// Double-buffered cp.async; smem rows padded to 144B (conflict-free fragment LDS).
// MODE 0: plain A rows. MODE 1: A gathered via g_perm, per-expert B (w1). MODE 2: compact A, per-expert B (w2).
// GELU => gelu applied; OUTH => store fp16 (rn), else fp32.
#define ROWB 144
#define STAGE_BYTES (128 * ROWB)      // 18432
#define SM_A 0
#define SM_B (2 * STAGE_BYTES)
#define GEMM_SMEM (4 * STAGE_BYTES)   // 73728

template <int MODE, bool GELU, bool OUTH>
__global__ __launch_bounds__(256, 2)
void mma_gemm(const __half* __restrict__ A, const __half* __restrict__ Bw,
              const float* __restrict__ bias, void* __restrict__ Cv,
              int N, int Kd) {
    int tileM = blockIdx.y, tileN = blockIdx.x;
    int valid = 128;
    const __half* Bp = Bw;
    const float* bp = bias;
    if (MODE != 0) {
        int e = g_tile_expert[tileM];
        if (e < 0) return;
        valid = g_tile_rows[tileM];
        if (MODE == 1) { Bp = Bw + (size_t)e * HH * DD; bp = bias + (size_t)e * HH; }
        else           { Bp = Bw + (size_t)e * OO * HH; bp = bias + (size_t)e * OO; }
    }
    int row0 = tileM * 128, col0 = tileN * 128;
    int tid = threadIdx.x;
    int wid = tid >> 5, lane = tid & 31;
    int gid = lane >> 2, tig = lane & 3;
    int warpM = wid & 3, warpN = wid >> 2;

    extern __shared__ char smem[];
    uint32_t sb = smem_u32(smem);

    // loader: thread covers row (tid>>1), 4 chunks of 8 halves at (tid&1)*32
    int lrow = tid >> 1;
    int lko  = (tid & 1) * 32;
    const __half* aSrc;
    if (MODE == 1) {
        int mc = (lrow < valid) ? lrow : (valid - 1);
        aSrc = A + (size_t)g_perm[row0 + mc] * Kd;
    } else {
        aSrc = A + (size_t)(row0 + lrow) * Kd;
    }
    const __half* bSrc = Bp + (size_t)(col0 + lrow) * Kd;

    auto load_stage = [&](int kt, int buf) {   // kt in halves
        uint32_t aB = sb + SM_A + buf * STAGE_BYTES + lrow * ROWB + lko * 2;
        uint32_t bB = sb + SM_B + buf * STAGE_BYTES + lrow * ROWB + lko * 2;
        #pragma unroll
        for (int i = 0; i < 4; i++) {
            cpa16(aB + i * 16, aSrc + kt + lko + i * 8);
            cpa16(bB + i * 16, bSrc + kt + lko + i * 8);
        }
        CP_COMMIT();
    };

    float acc[2][8][4];
    #pragma unroll
    for (int mi = 0; mi < 2; mi++)
        #pragma unroll
        for (int nj = 0; nj < 8; nj++)
            #pragma unroll
            for (int q = 0; q < 4; q++) acc[mi][nj][q] = 0.f;

    int NK = Kd >> 6;   // stages of 64 halves
    load_stage(0, 0);

    for (int kt = 0; kt < NK; kt++) {
        int buf = kt & 1;
        if (kt + 1 < NK) load_stage((kt + 1) << 6, (kt + 1) & 1);
        else CP_COMMIT();
        CP_WAIT1();
        __syncthreads();

        const char* As = smem + SM_A + buf * STAGE_BYTES;
        const char* Bs = smem + SM_B + buf * STAGE_BYTES;
        #pragma unroll
        for (int k16 = 0; k16 < 4; k16++) {
            int kb = (k16 * 16 + 2 * tig) * 2;   // byte offset of this thread's k pair
            uint32_t af[2][4], bf[8][2];
            #pragma unroll
            for (int mi = 0; mi < 2; mi++) {
                int m = warpM * 32 + mi * 16 + gid;
                af[mi][0] = *(const uint32_t*)(As + m * ROWB + kb);
                af[mi][1] = *(const uint32_t*)(As + (m + 8) * ROWB + kb);
                af[mi][2] = *(const uint32_t*)(As + m * ROWB + kb + 16);
                af[mi][3] = *(const uint32_t*)(As + (m + 8) * ROWB + kb + 16);
            }
            #pragma unroll
            for (int nj = 0; nj < 8; nj++) {
                int n = warpN * 64 + nj * 8 + gid;
                bf[nj][0] = *(const uint32_t*)(Bs + n * ROWB + kb);
                bf[nj][1] = *(const uint32_t*)(Bs + n * ROWB + kb + 16);
            }
            #pragma unroll
            for (int mi = 0; mi < 2; mi++)
                #pragma unroll
                for (int nj = 0; nj < 8; nj++)
                    MMA_F16(acc[mi][nj], af[mi], bf[nj]);
        }
        __syncthreads();
    }

    // ---- epilogue ----
    #pragma unroll
    for (int mi = 0; mi < 2; mi++) {
        int li0 = warpM * 32 + mi * 16 + gid;
        int li1 = li0 + 8;
        bool ok0 = (MODE == 0) || (li0 < valid);
        bool ok1 = (MODE == 0) || (li1 < valid);
        #pragma unroll
        for (int nj = 0; nj < 8; nj++) {
            int c = warpN * 64 + nj * 8 + tig * 2;
            float b0 = bp[col0 + c], b1 = bp[col0 + c + 1];
            float v0 = acc[mi][nj][0] + b0;
            float v1 = acc[mi][nj][1] + b1;
            float v2 = acc[mi][nj][2] + b0;
            float v3 = acc[mi][nj][3] + b1;
            if (GELU) {
                v0 = gelu_exact(v0); v1 = gelu_exact(v1);
                v2 = gelu_exact(v2); v3 = gelu_exact(v3);
            }
            if (OUTH) {
                __half* C = (__half*)Cv;
                __half* c0row = C + (size_t)(row0 + li0) * N + col0;
                __half* c1row = C + (size_t)(row0 + li1) * N + col0;
                if (ok0) *(__half2*)(c0row + c) = __floats2half2_rn(v0, v1);
                if (ok1) *(__half2*)(c1row + c) = __floats2half2_rn(v2, v3);
            } else {
                float* C = (float*)Cv;
                float* c0row = C + (size_t)(row0 + li0) * N + col0;
                float* c1row = C + (size_t)(row0 + li1) * N + col0;
                if (ok0) *(float2*)(c0row + c) = make_float2(v0, v1);
                if (ok1) *(float2*)(c1row + c) = make_float2(v2, v3);
            }
        }
    }
}

// ---------------- combine + LN2 ----------------
__global__ void combine_kernel(const float* __restrict__ g2,
                               const float* __restrict__ b2,
                               float* __restrict__ out) {
    int t = blockIdx.x, tid = threadIdx.x;
    int r0 = g_rank[2 * t], r1 = g_rank[2 * t + 1];
    float w0 = g_tkw[2 * t], w1 = g_tkw[2 * t + 1];
    const float* sh = g_sh + (size_t)t * OO;
    const float* e0 = g_eout2 + (size_t)r0 * OO;
    const float* e1 = g_eout2 + (size_t)r1 * OO;
    float v[4], s = 0.f, s2 = 0.f;
    #pragma unroll
    for (int i = 0; i < 4; i++) {
        int o = tid + i * 256;
        v[i] = sh[o] * (1.0f / 9.0f) + w0 * e0[o] + w1 * e1[o];
        s += v[i]; s2 += v[i] * v[i];
    }
    __shared__ float shm[16];
    block_reduce2(s, s2, shm);
    float m   = s  * (1.0f / OO);
    float var = s2 * (1.0f / OO) - m * m;
    float inv = rsqrtf(var + 1e-5f);
    float* orow = out + (size_t)t * OO;
    #pragma unroll
    for (int i = 0; i < 4; i++) {
        int o = tid + i * 256;
        orow[o] = (v[i] - m) * inv * g2[o] + b2[o];
    }
}

// ---------------- launch ----------------
extern "C" void kernel_launch(void* const* d_in, const int* in_sizes, int n_in,
                              void* d_out, int out_size) {
    const float* x        = (const float*)d_in[0];
    const float* ln1_g    = (const float*)d_in[1];
    const float* ln1_b    = (const float*)d_in[2];
    const float* router_w = (const float*)d_in[3];
    const float* router_b = (const float*)d_in[4];
    const float* sh_w1    = (const float*)d_in[5];
    const float* sh_b1    = (const float*)d_in[6];
    const float* sh_w2    = (const float*)d_in[7];
    const float* sh_b2    = (const float*)d_in[8];
    const float* e_w1     = (const float*)d_in[9];
    const float* e_b1     = (const float*)d_in[10];
    const float* e_w2     = (const float*)d_in[11];
    const float* e_b2     = (const float*)d_in[12];
    const float* ln2_g    = (const float*)d_in[13];
    const float* ln2_b    = (const float*)d_in[14];
    float* out = (float*)d_out;

    __half *p_xh, *p_h1h, *p_hid2h, *p_w1h, *p_w2h, *p_sw1h, *p_sw2h;
    float *p_sh, *p_eout2;
    cudaGetSymbolAddress((void**)&p_xh,    g_xh);
    cudaGetSymbolAddress((void**)&p_h1h,   g_h1h);
    cudaGetSymbolAddress((void**)&p_sh,    g_sh);
    cudaGetSymbolAddress((void**)&p_hid2h, g_hid2h);
    cudaGetSymbolAddress((void**)&p_eout2, g_eout2);
    cudaGetSymbolAddress((void**)&p_w1h,   g_w1h);
    cudaGetSymbolAddress((void**)&p_w2h,   g_w2h);
    cudaGetSymbolAddress((void**)&p_sw1h,  g_sw1h);
    cudaGetSymbolAddress((void**)&p_sw2h,  g_sw2h);

    cudaFuncSetAttribute(mma_gemm<0, true , true >, cudaFuncAttributeMaxDynamicSharedMemorySize, GEMM_SMEM);
    cudaFuncSetAttribute(mma_gemm<0, false, false>, cudaFuncAttributeMaxDynamicSharedMemorySize, GEMM_SMEM);
    cudaFuncSetAttribute(mma_gemm<1, true , true >, cudaFuncAttributeMaxDynamicSharedMemorySize, GEMM_SMEM);
    cudaFuncSetAttribute(mma_gemm<2, false, false>, cudaFuncAttributeMaxDynamicSharedMemorySize, GEMM_SMEM);

    // fp32 -> fp16 weight conversion (also resets counts)
    {
        int n8;
        n8 = EE * HH * DD / 8; cvt_f2h_kernel<<<(n8 + 255) / 256, 256>>>((const float4*)e_w1, (uint4*)p_w1h, n8);
        n8 = EE * OO * HH / 8; cvt_f2h_kernel<<<(n8 + 255) / 256, 256>>>((const float4*)e_w2, (uint4*)p_w2h, n8);
        n8 = HH * DD / 8;      cvt_f2h_kernel<<<(n8 + 255) / 256, 256>>>((const float4*)sh_w1, (uint4*)p_sw1h, n8);
        n8 = OO * HH / 8;      cvt_f2h_kernel<<<(n8 + 255) / 256, 256>>>((const float4*)sh_w2, (uint4*)p_sw2h, n8);
    }

    ln1_router_kernel<<<TT, 256>>>(x, ln1_g, ln1_b, router_w, router_b);
    prefix_kernel<<<1, 1>>>();
    place_kernel<<<(TT * 2) / 256, 256>>>();

    // shared GEMM1 (GELU, half out): [T,H] = xh @ sw1^T
    mma_gemm<0, true , true ><<<dim3(HH / 128, TT / 128), 256, GEMM_SMEM>>>(p_xh, p_sw1h, sh_b1, p_h1h, HH, DD);
    // shared GEMM2 (fp32 out): [T,O] = h1 @ sw2^T
    mma_gemm<0, false, false><<<dim3(OO / 128, TT / 128), 256, GEMM_SMEM>>>(p_h1h, p_sw2h, sh_b2, p_sh, OO, HH);
    // expert GEMM1 (gathered, GELU, half out): hid2 = xh[perm] @ w1h[e]^T
    mma_gemm<1, true , true ><<<dim3(HH / 128, MAXTILES), 256, GEMM_SMEM>>>(p_xh, p_w1h, e_b1, p_hid2h, HH, DD);
    // expert GEMM2 (fp32 out): eout2 = hid2 @ w2h[e]^T
    mma_gemm<2, false, false><<<dim3(OO / 128, MAXTILES), 256, GEMM_SMEM>>>(p_hid2h, p_w2h, e_b2, p_eout2, OO, HH);

    combine_kernel<<<TT, 256>>>(ln2_g, ln2_b, out);
}

// round 7
// speedup vs baseline: 4.2981x; 1.0112x over previous
#include <cuda_runtime.h>
#include <cuda_fp16.h>
#include <math.h>
#include <stdint.h>

// ---------------- compile-time problem shape ----------------
#define TT 4096    // B*S tokens
#define DD 1024
#define HH 2048
#define OO 1024
#define EE 8
#define MAXTILES 72
#define BUFROWS (MAXTILES*128)

// ---------------- scratch (device globals) ----------------
__device__ __half g_xh  [(size_t)TT*DD];       // LN1 output (fp16)
__device__ __half g_h1h [(size_t)TT*HH];       // shared expert hidden (fp16)
__device__ float  g_sh  [(size_t)TT*OO];       // shared expert output (fp32)
__device__ __half g_hid2h[(size_t)BUFROWS*HH]; // expert hidden, compact (fp16)
__device__ float  g_eout2[(size_t)BUFROWS*OO]; // expert output, compact (fp32)
__device__ __half g_w1h [(size_t)EE*HH*DD];
__device__ __half g_w2h [(size_t)EE*OO*HH];
__device__ __half g_sw1h[(size_t)HH*DD];
__device__ __half g_sw2h[(size_t)OO*HH];

__device__ int   g_tki [TT*2];
__device__ float g_tkw [TT*2];
__device__ int   g_rank[TT*2];
__device__ int   g_perm[BUFROWS];
__device__ int   g_counts[EE];
__device__ int   g_cursor[EE];
__device__ int   g_base[EE];
__device__ int   g_tile_expert[MAXTILES];
__device__ int   g_tile_rows[MAXTILES];

// ---------------- PTX helpers (baseline features; legal on compute_103) ----------------
__device__ __forceinline__ uint32_t smem_u32(const void* p) {
    uint32_t a;
    asm("{ .reg .u64 t; cvta.to.shared.u64 t, %1; cvt.u32.u64 %0, t; }" : "=r"(a) : "l"(p));
    return a;
}
__device__ __forceinline__ void cpa16(uint32_t dst, const void* src) {
    asm volatile("cp.async.cg.shared.global [%0], [%1], 16;" :: "r"(dst), "l"(src));
}
#define CP_COMMIT()  asm volatile("cp.async.commit_group;" ::: "memory")
#define CP_WAIT1()   asm volatile("cp.async.wait_group 1;" ::: "memory")

#define MMA_F16(c, a, b) \
    asm volatile("mma.sync.aligned.m16n8k16.row.col.f32.f16.f16.f32 " \
        "{%0,%1,%2,%3}, {%4,%5,%6,%7}, {%8,%9}, {%0,%1,%2,%3};" \
        : "+f"((c)[0]), "+f"((c)[1]), "+f"((c)[2]), "+f"((c)[3]) \
        : "r"((a)[0]), "r"((a)[1]), "r"((a)[2]), "r"((a)[3]), \
          "r"((b)[0]), "r"((b)[1]))

#define LDSM_X4(r0, r1, r2, r3, addr) \
    asm volatile("ldmatrix.sync.aligned.m8n8.x4.shared.b16 {%0,%1,%2,%3}, [%4];" \
        : "=r"(r0), "=r"(r1), "=r"(r2), "=r"(r3) : "r"(addr))

__device__ __forceinline__ float gelu_exact(float x) {
    return 0.5f * x * (1.0f + erff(x * 0.70710678118654752440f));
}

__device__ __forceinline__ void block_reduce2(float& s, float& s2, float* sh) {
    #pragma unroll
    for (int o = 16; o; o >>= 1) {
        s  += __shfl_down_sync(0xffffffffu, s,  o);
        s2 += __shfl_down_sync(0xffffffffu, s2, o);
    }
    int w = threadIdx.x >> 5, l = threadIdx.x & 31;
    if (l == 0) { sh[w] = s; sh[8 + w] = s2; }
    __syncthreads();
    if (threadIdx.x == 0) {
        float a = 0.f, b = 0.f;
        #pragma unroll
        for (int i = 0; i < 8; i++) { a += sh[i]; b += sh[8 + i]; }
        sh[0] = a; sh[8] = b;
    }
    __syncthreads();
    s = sh[0]; s2 = sh[8];
}

// ---------------- fused fp32->fp16 convert of ALL weights (+ counter reset) ----------------
#define N8_EW1 (EE*HH*DD/8)
#define N8_EW2 (EE*OO*HH/8)
#define N8_SW1 (HH*DD/8)
#define N8_SW2 (OO*HH/8)
#define N8_ALL (N8_EW1 + N8_EW2 + N8_SW1 + N8_SW2)

__global__ void cvt_all_kernel(const float4* __restrict__ ew1, const float4* __restrict__ ew2,
                               const float4* __restrict__ sw1, const float4* __restrict__ sw2) {
    if (blockIdx.x == 0 && threadIdx.x < EE) g_counts[threadIdx.x] = 0;
    int i = blockIdx.x * blockDim.x + threadIdx.x;
    if (i >= N8_ALL) return;
    const float4* src; uint4* dst; int j = i;
    if (j < N8_EW1)                 { src = ew1; dst = (uint4*)g_w1h; }
    else if ((j -= N8_EW1) < N8_EW2){ src = ew2; dst = (uint4*)g_w2h; }
    else if ((j -= N8_EW2) < N8_SW1){ src = sw1; dst = (uint4*)g_sw1h; }
    else { j -= N8_SW1;               src = sw2; dst = (uint4*)g_sw2h; }
    float4 v0 = src[2 * j], v1 = src[2 * j + 1];
    __half2 h0 = __floats2half2_rn(v0.x, v0.y);
    __half2 h1 = __floats2half2_rn(v0.z, v0.w);
    __half2 h2 = __floats2half2_rn(v1.x, v1.y);
    __half2 h3 = __floats2half2_rn(v1.z, v1.w);
    uint4 w;
    w.x = *(uint32_t*)&h0; w.y = *(uint32_t*)&h1;
    w.z = *(uint32_t*)&h2; w.w = *(uint32_t*)&h3;
    dst[j] = w;
}

// ---------------- fused LN1 + router (one block / token) ----------------
__global__ void ln1_router_kernel(const float* __restrict__ x,
                                  const float* __restrict__ g,
                                  const float* __restrict__ b,
                                  const float* __restrict__ rw,
                                  const float* __restrict__ rb) {
    int t = blockIdx.x, tid = threadIdx.x;
    const float* xr = x + (size_t)t * DD;
    float v[4], s = 0.f, s2 = 0.f;
    #pragma unroll
    for (int i = 0; i < 4; i++) {
        v[i] = xr[tid + i * 256];
        s += v[i]; s2 += v[i] * v[i];
    }
    __shared__ float sh[16];
    block_reduce2(s, s2, sh);
    float m   = s  * (1.0f / DD);
    float var = s2 * (1.0f / DD) - m * m;
    float inv = rsqrtf(var + 1e-5f);

    __half* yr = g_xh + (size_t)t * DD;
    float p[EE];
    #pragma unroll
    for (int e = 0; e < EE; e++) p[e] = 0.f;
    #pragma unroll
    for (int i = 0; i < 4; i++) {
        int d = tid + i * 256;
        float y = (v[i] - m) * inv * g[d] + b[d];
        yr[d] = __float2half_rn(y);
        #pragma unroll
        for (int e = 0; e < EE; e++) p[e] += y * rw[e * DD + d];
    }
    __shared__ float sl[256][EE];
    #pragma unroll
    for (int e = 0; e < EE; e++) sl[tid][e] = p[e];
    __syncthreads();
    for (int o = 128; o; o >>= 1) {
        if (tid < o) {
            #pragma unroll
            for (int e = 0; e < EE; e++) sl[tid][e] += sl[tid + o][e];
        }
        __syncthreads();
    }
    if (tid == 0) {
        float l[EE];
        #pragma unroll
        for (int e = 0; e < EE; e++) l[e] = sl[0][e] + rb[e];
        int i0 = 0;
        #pragma unroll
        for (int e = 1; e < EE; e++) if (l[e] > l[i0]) i0 = e;
        int i1 = (i0 == 0) ? 1 : 0;
        #pragma unroll
        for (int e = 0; e < EE; e++) if (e != i0 && l[e] > l[i1]) i1 = e;
        float e1 = expf(l[i1] - l[i0]);
        float invp = 1.0f / (1.0f + e1);
        g_tki[2 * t] = i0;  g_tki[2 * t + 1] = i1;
        g_tkw[2 * t] = invp; g_tkw[2 * t + 1] = e1 * invp;
        atomicAdd(&g_counts[i0], 1);
        atomicAdd(&g_counts[i1], 1);
    }
}

// ---------------- segment prefix ----------------
__global__ void prefix_kernel() {
    int rowbase = 0, tile = 0;
    for (int e = 0; e < EE; e++) {
        int cnt = g_counts[e];
        g_base[e] = rowbase;
        g_cursor[e] = 0;
        int nt = (cnt + 127) >> 7;
        for (int j = 0; j < nt; j++) {
            g_tile_expert[tile] = e;
            int rem = cnt - j * 128;
            g_tile_rows[tile] = rem < 128 ? rem : 128;
            tile++;
        }
        rowbase += nt << 7;
    }
    for (; tile < MAXTILES; tile++) { g_tile_expert[tile] = -1; g_tile_rows[tile] = 0; }
}

// ---------------- placement ----------------
__global__ void place_kernel() {
    int i = blockIdx.x * blockDim.x + threadIdx.x;
    if (i >= TT * 2) return;
    int e = g_tki[i];
    int pos = g_base[e] + atomicAdd(&g_cursor[e], 1);
    g_perm[pos] = i >> 1;
    g_rank[i] = pos;
}

// ============ fp16 mma.sync GEMM: C[M,N] = A[M,K] @ B[N,K]^T + bias ============
// BM=128, BN=256, BK=64 halves. 256 threads = 8 warps (2 in M x 4 in N), warp tile 64x64.
// Fragments via ldmatrix.x4; rows padded to 144B (conflict-free LDSM phases).
// Double-buffered cp.async.
#define ROWB 144
#define A_STAGE (128 * ROWB)          // 18432
#define B_STAGE (256 * ROWB)          // 36864
#define SM_A 0
#define SM_B (2 * A_STAGE)            // 36864
#define GEMM_SMEM (2 * A_STAGE + 2 * B_STAGE)  // 110592

template <int MODE, bool GELU, bool OUTH>
__global__ __launch_bounds__(256, 1)
void mma_gemm(const __half* __restrict__ A, const __half* __restrict__ Bw,
              const float* __restrict__ bias, void* __restrict__ Cv,
              int N, int Kd) {
    int tileM = blockIdx.y, tileN = blockIdx.x;
    int valid = 128;
    const __half* Bp = Bw;
    const float* bp = bias;
    if (MODE != 0) {
        int e = g_tile_expert[tileM];
        if (e < 0) return;
        valid = g_tile_rows[tileM];
        if (MODE == 1) { Bp = Bw + (size_t)e * HH * DD; bp = bias + (size_t)e * HH; }
        else           { Bp = Bw + (size_t)e * OO * HH; bp = bias + (size_t)e * OO; }
    }
    int row0 = tileM * 128, col0 = tileN * 256;
    int tid = threadIdx.x;
    int wid = tid >> 5, lane = tid & 31;
    int gid = lane >> 2, tig = lane & 3;
    int warpM = wid & 1, warpN = wid >> 1;   // 2 x 4

    extern __shared__ char smem[];
    uint32_t sb = smem_u32(smem);

    // ---- loaders ----
    // A: thread covers row tid>>1, half-row (tid&1): 4 cpa16
    int arow = tid >> 1;
    int ahal = tid & 1;
    const __half* aSrc;
    if (MODE == 1) {
        int mc = (arow < valid) ? arow : (valid - 1);
        aSrc = A + (size_t)g_perm[row0 + mc] * Kd;
    } else {
        aSrc = A + (size_t)(row0 + arow) * Kd;
    }
    // B: thread covers row tid: 8 cpa16
    const __half* bSrc = Bp + (size_t)(col0 + tid) * Kd;

    auto load_stage = [&](int kt, int buf) {   // kt in halves
        uint32_t aB = sb + SM_A + buf * A_STAGE + arow * ROWB + ahal * 64;
        uint32_t bB = sb + SM_B + buf * B_STAGE + tid * ROWB;
        const __half* ap = aSrc + kt + ahal * 32;
        const __half* bpS = bSrc + kt;
        #pragma unroll
        for (int i = 0; i < 4; i++) cpa16(aB + i * 16, ap + i * 8);
        #pragma unroll
        for (int i = 0; i < 8; i++) cpa16(bB + i * 16, bpS + i * 8);
        CP_COMMIT();
    };

    // ---- per-lane ldmatrix base offsets (within a stage buffer) ----
    // A (per mi): rows warpM*64 + mi*16 + (lane&15), koff (lane>>4)*16
    uint32_t aLdsmOff[4];
    #pragma unroll
    for (int mi = 0; mi < 4; mi++)
        aLdsmOff[mi] = (uint32_t)(warpM * 64 + mi * 16 + (lane & 15)) * ROWB + (lane >> 4) * 16;
    // B (per nj-pair p): rows warpN*64 + p*16 + (lane>>4)*8 + (lane&7), koff ((lane>>3)&1)*16
    uint32_t bLdsmOff[4];
    #pragma unroll
    for (int p = 0; p < 4; p++)
        bLdsmOff[p] = (uint32_t)(warpN * 64 + p * 16 + ((lane >> 4) << 3) + (lane & 7)) * ROWB
                    + ((lane >> 3) & 1) * 16;

    float acc[4][8][4];
    #pragma unroll
    for (int mi = 0; mi < 4; mi++)
        #pragma unroll
        for (int nj = 0; nj < 8; nj++)
            #pragma unroll
            for (int q = 0; q < 4; q++) acc[mi][nj][q] = 0.f;

    int NK = Kd >> 6;   // stages of 64 halves
    load_stage(0, 0);

    for (int kt = 0; kt < NK; kt++) {
        int buf = kt & 1;
        if (kt + 1 < NK) load_stage((kt + 1) << 6, (kt + 1) & 1);
        else CP_COMMIT();
        CP_WAIT1();
        __syncthreads();

        uint32_t aBase = sb + SM_A + buf * A_STAGE;
        uint32_t bBase = sb + SM_B + buf * B_STAGE;
        #pragma unroll
        for (int k16 = 0; k16 < 4; k16++) {
            uint32_t kb = k16 * 32;
            uint32_t af[4][4], bf[8][2];
            #pragma unroll
            for (int mi = 0; mi < 4; mi++)
                LDSM_X4(af[mi][0], af[mi][1], af[mi][2], af[mi][3], aBase + aLdsmOff[mi] + kb);
            #pragma unroll
            for (int p = 0; p < 4; p++)
                LDSM_X4(bf[2 * p][0], bf[2 * p][1], bf[2 * p + 1][0], bf[2 * p + 1][1],
                        bBase + bLdsmOff[p] + kb);
            #pragma unroll
            for (int mi = 0; mi < 4; mi++)
                #pragma unroll
                for (int nj = 0; nj < 8; nj++)
                    MMA_F16(acc[mi][nj], af[mi], bf[nj]);
        }
        __syncthreads();
    }

    // ---- epilogue ----
    #pragma unroll
    for (int mi = 0; mi < 4; mi++) {
        int li0 = warpM * 64 + mi * 16 + gid;
        int li1 = li0 + 8;
        bool ok0 = (MODE == 0) || (li0 < valid);
        bool ok1 = (MODE == 0) || (li1 < valid);
        #pragma unroll
        for (int nj = 0; nj < 8; nj++) {
            int c = warpN * 64 + nj * 8 + tig * 2;
            float b0 = bp[col0 + c], b1 = bp[col0 + c + 1];
            float v0 = acc[mi][nj][0] + b0;
            float v1 = acc[mi][nj][1] + b1;
            float v2 = acc[mi][nj][2] + b0;
            float v3 = acc[mi][nj][3] + b1;
            if (GELU) {
                v0 = gelu_exact(v0); v1 = gelu_exact(v1);
                v2 = gelu_exact(v2); v3 = gelu_exact(v3);
            }
            if (OUTH) {
                __half* C = (__half*)Cv;
                if (ok0) *(__half2*)(C + (size_t)(row0 + li0) * N + col0 + c) = __floats2half2_rn(v0, v1);
                if (ok1) *(__half2*)(C + (size_t)(row0 + li1) * N + col0 + c) = __floats2half2_rn(v2, v3);
            } else {
                float* C = (float*)Cv;
                if (ok0) *(float2*)(C + (size_t)(row0 + li0) * N + col0 + c) = make_float2(v0, v1);
                if (ok1) *(float2*)(C + (size_t)(row0 + li1) * N + col0 + c) = make_float2(v2, v3);
            }
        }
    }
}

// ---------------- combine + LN2 ----------------
__global__ void combine_kernel(const float* __restrict__ g2,
                               const float* __restrict__ b2,
                               float* __restrict__ out) {
    int t = blockIdx.x, tid = threadIdx.x;
    int r0 = g_rank[2 * t], r1 = g_rank[2 * t + 1];
    float w0 = g_tkw[2 * t], w1 = g_tkw[2 * t + 1];
    const float* sh = g_sh + (size_t)t * OO;
    const float* e0 = g_eout2 + (size_t)r0 * OO;
    const float* e1 = g_eout2 + (size_t)r1 * OO;
    float v[4], s = 0.f, s2 = 0.f;
    #pragma unroll
    for (int i = 0; i < 4; i++) {
        int o = tid + i * 256;
        v[i] = sh[o] * (1.0f / 9.0f) + w0 * e0[o] + w1 * e1[o];
        s += v[i]; s2 += v[i] * v[i];
    }
    __shared__ float shm[16];
    block_reduce2(s, s2, shm);
    float m   = s  * (1.0f / OO);
    float var = s2 * (1.0f / OO) - m * m;
    float inv = rsqrtf(var + 1e-5f);
    float* orow = out + (size_t)t * OO;
    #pragma unroll
    for (int i = 0; i < 4; i++) {
        int o = tid + i * 256;
        orow[o] = (v[i] - m) * inv * g2[o] + b2[o];
    }
}

// ---------------- launch ----------------
extern "C" void kernel_launch(void* const* d_in, const int* in_sizes, int n_in,
                              void* d_out, int out_size) {
    const float* x        = (const float*)d_in[0];
    const float* ln1_g    = (const float*)d_in[1];
    const float* ln1_b    = (const float*)d_in[2];
    const float* router_w = (const float*)d_in[3];
    const float* router_b = (const float*)d_in[4];
    const float* sh_w1    = (const float*)d_in[5];
    const float* sh_b1    = (const float*)d_in[6];
    const float* sh_w2    = (const float*)d_in[7];
    const float* sh_b2    = (const float*)d_in[8];
    const float* e_w1     = (const float*)d_in[9];
    const float* e_b1     = (const float*)d_in[10];
    const float* e_w2     = (const float*)d_in[11];
    const float* e_b2     = (const float*)d_in[12];
    const float* ln2_g    = (const float*)d_in[13];
    const float* ln2_b    = (const float*)d_in[14];
    float* out = (float*)d_out;

    __half *p_xh, *p_h1h, *p_hid2h, *p_w1h, *p_w2h, *p_sw1h, *p_sw2h;
    float *p_sh, *p_eout2;
    cudaGetSymbolAddress((void**)&p_xh,    g_xh);
    cudaGetSymbolAddress((void**)&p_h1h,   g_h1h);
    cudaGetSymbolAddress((void**)&p_sh,    g_sh);
    cudaGetSymbolAddress((void**)&p_hid2h, g_hid2h);
    cudaGetSymbolAddress((void**)&p_eout2, g_eout2);
    cudaGetSymbolAddress((void**)&p_w1h,   g_w1h);
    cudaGetSymbolAddress((void**)&p_w2h,   g_w2h);
    cudaGetSymbolAddress((void**)&p_sw1h,  g_sw1h);
    cudaGetSymbolAddress((void**)&p_sw2h,  g_sw2h);

    cudaFuncSetAttribute(mma_gemm<0, true , true >, cudaFuncAttributeMaxDynamicSharedMemorySize, GEMM_SMEM);
    cudaFuncSetAttribute(mma_gemm<0, false, false>, cudaFuncAttributeMaxDynamicSharedMemorySize, GEMM_SMEM);
    cudaFuncSetAttribute(mma_gemm<1, true , true >, cudaFuncAttributeMaxDynamicSharedMemorySize, GEMM_SMEM);
    cudaFuncSetAttribute(mma_gemm<2, false, false>, cudaFuncAttributeMaxDynamicSharedMemorySize, GEMM_SMEM);

    // all weights fp32 -> fp16 in one pass (also resets counts)
    cvt_all_kernel<<<(N8_ALL + 255) / 256, 256>>>((const float4*)e_w1, (const float4*)e_w2,
                                                  (const float4*)sh_w1, (const float4*)sh_w2);

    ln1_router_kernel<<<TT, 256>>>(x, ln1_g, ln1_b, router_w, router_b);
    prefix_kernel<<<1, 1>>>();
    place_kernel<<<(TT * 2) / 256, 256>>>();

    // shared GEMM1 (GELU, half out): [T,H] = xh @ sw1^T
    mma_gemm<0, true , true ><<<dim3(HH / 256, TT / 128), 256, GEMM_SMEM>>>(p_xh, p_sw1h, sh_b1, p_h1h, HH, DD);
    // shared GEMM2 (fp32 out): [T,O] = h1 @ sw2^T
    mma_gemm<0, false, false><<<dim3(OO / 256, TT / 128), 256, GEMM_SMEM>>>(p_h1h, p_sw2h, sh_b2, p_sh, OO, HH);
    // expert GEMM1 (gathered, GELU, half out): hid2 = xh[perm] @ w1h[e]^T
    mma_gemm<1, true , true ><<<dim3(HH / 256, MAXTILES), 256, GEMM_SMEM>>>(p_xh, p_w1h, e_b1, p_hid2h, HH, DD);
    // expert GEMM2 (fp32 out): eout2 = hid2 @ w2h[e]^T
    mma_gemm<2, false, false><<<dim3(OO / 256, MAXTILES), 256, GEMM_SMEM>>>(p_hid2h, p_w2h, e_b2, p_eout2, OO, HH);

    combine_kernel<<<TT, 256>>>(ln2_g, ln2_b, out);
}

// round 8
// speedup vs baseline: 4.3155x; 1.0041x over previous
#include <cuda_runtime.h>
#include <cuda_fp16.h>
#include <math.h>
#include <stdint.h>

// ---------------- compile-time problem shape ----------------
#define TT 4096    // B*S tokens
#define DD 1024
#define HH 2048
#define OO 1024
#define EE 8
#define MAXTILES 72
#define BUFROWS (MAXTILES*128)

// ---------------- scratch (device globals) ----------------
__device__ __half g_xh  [(size_t)TT*DD];       // LN1 output (fp16)
__device__ __half g_h1h [(size_t)TT*HH];       // shared expert hidden (fp16)
__device__ float  g_sh  [(size_t)TT*OO];       // shared expert output (fp32)
__device__ __half g_hid2h[(size_t)BUFROWS*HH]; // expert hidden, compact (fp16)
__device__ float  g_eout2[(size_t)BUFROWS*OO]; // expert output, compact (fp32)
__device__ __half g_w1h [(size_t)EE*HH*DD];
__device__ __half g_w2h [(size_t)EE*OO*HH];
__device__ __half g_sw1h[(size_t)HH*DD];
__device__ __half g_sw2h[(size_t)OO*HH];

__device__ int   g_tki [TT*2];
__device__ float g_tkw [TT*2];
__device__ int   g_rank[TT*2];
__device__ int   g_perm[BUFROWS];
__device__ int   g_counts[EE];
__device__ int   g_cursor[EE];
__device__ int   g_base[EE];
__device__ int   g_tile_expert[MAXTILES];
__device__ int   g_tile_rows[MAXTILES];

// ---------------- PTX helpers (baseline features; legal on compute_103) ----------------
__device__ __forceinline__ uint32_t smem_u32(const void* p) {
    uint32_t a;
    asm("{ .reg .u64 t; cvta.to.shared.u64 t, %1; cvt.u32.u64 %0, t; }" : "=r"(a) : "l"(p));
    return a;
}
__device__ __forceinline__ void cpa16(uint32_t dst, const void* src) {
    asm volatile("cp.async.cg.shared.global [%0], [%1], 16;" :: "r"(dst), "l"(src));
}
#define CP_COMMIT()  asm volatile("cp.async.commit_group;" ::: "memory")
#define CP_WAIT1()   asm volatile("cp.async.wait_group 1;" ::: "memory")

#define MMA_F16(c, a, b) \
    asm volatile("mma.sync.aligned.m16n8k16.row.col.f32.f16.f16.f32 " \
        "{%0,%1,%2,%3}, {%4,%5,%6,%7}, {%8,%9}, {%0,%1,%2,%3};" \
        : "+f"((c)[0]), "+f"((c)[1]), "+f"((c)[2]), "+f"((c)[3]) \
        : "r"((a)[0]), "r"((a)[1]), "r"((a)[2]), "r"((a)[3]), \
          "r"((b)[0]), "r"((b)[1]))

#define LDSM_X4(r0, r1, r2, r3, addr) \
    asm volatile("ldmatrix.sync.aligned.m8n8.x4.shared.b16 {%0,%1,%2,%3}, [%4];" \
        : "=r"(r0), "=r"(r1), "=r"(r2), "=r"(r3) : "r"(addr))

__device__ __forceinline__ float gelu_exact(float x) {
    return 0.5f * x * (1.0f + erff(x * 0.70710678118654752440f));
}

__device__ __forceinline__ void block_reduce2(float& s, float& s2, float* sh) {
    #pragma unroll
    for (int o = 16; o; o >>= 1) {
        s  += __shfl_down_sync(0xffffffffu, s,  o);
        s2 += __shfl_down_sync(0xffffffffu, s2, o);
    }
    int w = threadIdx.x >> 5, l = threadIdx.x & 31;
    if (l == 0) { sh[w] = s; sh[8 + w] = s2; }
    __syncthreads();
    if (threadIdx.x == 0) {
        float a = 0.f, b = 0.f;
        #pragma unroll
        for (int i = 0; i < 8; i++) { a += sh[i]; b += sh[8 + i]; }
        sh[0] = a; sh[8] = b;
    }
    __syncthreads();
    s = sh[0]; s2 = sh[8];
}

// ---------------- fused fp32->fp16 convert of ALL weights (+ counter reset) ----------------
#define N8_EW1 (EE*HH*DD/8)
#define N8_EW2 (EE*OO*HH/8)
#define N8_SW1 (HH*DD/8)
#define N8_SW2 (OO*HH/8)
#define N8_ALL (N8_EW1 + N8_EW2 + N8_SW1 + N8_SW2)

__global__ void cvt_all_kernel(const float4* __restrict__ ew1, const float4* __restrict__ ew2,
                               const float4* __restrict__ sw1, const float4* __restrict__ sw2) {
    if (blockIdx.x == 0 && threadIdx.x < EE) g_counts[threadIdx.x] = 0;
    int i = blockIdx.x * blockDim.x + threadIdx.x;
    if (i >= N8_ALL) return;
    const float4* src; uint4* dst; int j = i;
    if (j < N8_EW1)                 { src = ew1; dst = (uint4*)g_w1h; }
    else if ((j -= N8_EW1) < N8_EW2){ src = ew2; dst = (uint4*)g_w2h; }
    else if ((j -= N8_EW2) < N8_SW1){ src = sw1; dst = (uint4*)g_sw1h; }
    else { j -= N8_SW1;               src = sw2; dst = (uint4*)g_sw2h; }
    float4 v0 = src[2 * j], v1 = src[2 * j + 1];
    __half2 h0 = __floats2half2_rn(v0.x, v0.y);
    __half2 h1 = __floats2half2_rn(v0.z, v0.w);
    __half2 h2 = __floats2half2_rn(v1.x, v1.y);
    __half2 h3 = __floats2half2_rn(v1.z, v1.w);
    uint4 w;
    w.x = *(uint32_t*)&h0; w.y = *(uint32_t*)&h1;
    w.z = *(uint32_t*)&h2; w.w = *(uint32_t*)&h3;
    dst[j] = w;
}

// ---------------- fused LN1 + router (one block / token) ----------------
__global__ void ln1_router_kernel(const float* __restrict__ x,
                                  const float* __restrict__ g,
                                  const float* __restrict__ b,
                                  const float* __restrict__ rw,
                                  const float* __restrict__ rb) {
    int t = blockIdx.x, tid = threadIdx.x;
    const float* xr = x + (size_t)t * DD;
    float v[4], s = 0.f, s2 = 0.f;
    #pragma unroll
    for (int i = 0; i < 4; i++) {
        v[i] = xr[tid + i * 256];
        s += v[i]; s2 += v[i] * v[i];
    }
    __shared__ float sh[16];
    block_reduce2(s, s2, sh);
    float m   = s  * (1.0f / DD);
    float var = s2 * (1.0f / DD) - m * m;
    float inv = rsqrtf(var + 1e-5f);

    __half* yr = g_xh + (size_t)t * DD;
    float p[EE];
    #pragma unroll
    for (int e = 0; e < EE; e++) p[e] = 0.f;
    #pragma unroll
    for (int i = 0; i < 4; i++) {
        int d = tid + i * 256;
        float y = (v[i] - m) * inv * g[d] + b[d];
        yr[d] = __float2half_rn(y);
        #pragma unroll
        for (int e = 0; e < EE; e++) p[e] += y * rw[e * DD + d];
    }
    __shared__ float sl[256][EE];
    #pragma unroll
    for (int e = 0; e < EE; e++) sl[tid][e] = p[e];
    __syncthreads();
    for (int o = 128; o; o >>= 1) {
        if (tid < o) {
            #pragma unroll
            for (int e = 0; e < EE; e++) sl[tid][e] += sl[tid + o][e];
        }
        __syncthreads();
    }
    if (tid == 0) {
        float l[EE];
        #pragma unroll
        for (int e = 0; e < EE; e++) l[e] = sl[0][e] + rb[e];
        int i0 = 0;
        #pragma unroll
        for (int e = 1; e < EE; e++) if (l[e] > l[i0]) i0 = e;
        int i1 = (i0 == 0) ? 1 : 0;
        #pragma unroll
        for (int e = 0; e < EE; e++) if (e != i0 && l[e] > l[i1]) i1 = e;
        float e1 = expf(l[i1] - l[i0]);
        float invp = 1.0f / (1.0f + e1);
        g_tki[2 * t] = i0;  g_tki[2 * t + 1] = i1;
        g_tkw[2 * t] = invp; g_tkw[2 * t + 1] = e1 * invp;
        atomicAdd(&g_counts[i0], 1);
        atomicAdd(&g_counts[i1], 1);
    }
}

// ---------------- segment prefix ----------------
__global__ void prefix_kernel() {
    int rowbase = 0, tile = 0;
    for (int e = 0; e < EE; e++) {
        int cnt = g_counts[e];
        g_base[e] = rowbase;
        g_cursor[e] = 0;
        int nt = (cnt + 127) >> 7;
        for (int j = 0; j < nt; j++) {
            g_tile_expert[tile] = e;
            int rem = cnt - j * 128;
            g_tile_rows[tile] = rem < 128 ? rem : 128;
            tile++;
        }
        rowbase += nt << 7;
    }
    for (; tile < MAXTILES; tile++) { g_tile_expert[tile] = -1; g_tile_rows[tile] = 0; }
}

// ---------------- placement ----------------
__global__ void place_kernel() {
    int i = blockIdx.x * blockDim.x + threadIdx.x;
    if (i >= TT * 2) return;
    int e = g_tki[i];
    int pos = g_base[e] + atomicAdd(&g_cursor[e], 1);
    g_perm[pos] = i >> 1;
    g_rank[i] = pos;
}

// ============ fp16 mma.sync GEMM: C[M,N] = A[M,K] @ B[N,K]^T + bias ============
// BM=128, BN=256, BK=64 halves. 256 threads = 8 warps (2 in M x 4 in N), warp tile 64x64.
// Fragments via ldmatrix.x4; rows padded to 144B (conflict-free LDSM phases).
// Double-buffered cp.async.
#define ROWB 144
#define A_STAGE (128 * ROWB)          // 18432
#define B_STAGE (256 * ROWB)          // 36864
#define SM_A 0
#define SM_B (2 * A_STAGE)            // 36864
#define GEMM_SMEM (2 * A_STAGE + 2 * B_STAGE)  // 110592

template <int MODE, bool GELU, bool OUTH>
__global__ __launch_bounds__(256, 1)
void mma_gemm(const __half* __restrict__ A, const __half* __restrict__ Bw,
              const float* __restrict__ bias, void* __restrict__ Cv,
              int N, int Kd) {
    int tileM = blockIdx.y, tileN = blockIdx.x;
    int valid = 128;
    const __half* Bp = Bw;
    const float* bp = bias;
    if (MODE != 0) {
        int e = g_tile_expert[tileM];
        if (e < 0) return;
        valid = g_tile_rows[tileM];
        if (MODE == 1) { Bp = Bw + (size_t)e * HH * DD; bp = bias + (size_t)e * HH; }
        else           { Bp = Bw + (size_t)e * OO * HH; bp = bias + (size_t)e * OO; }
    }
    int row0 = tileM * 128, col0 = tileN * 256;
    int tid = threadIdx.x;
    int wid = tid >> 5, lane = tid & 31;
    int gid = lane >> 2, tig = lane & 3;
    int warpM = wid & 1, warpN = wid >> 1;   // 2 x 4

    extern __shared__ char smem[];
    uint32_t sb = smem_u32(smem);

    // ---- loaders ----
    // A: thread covers row tid>>1, half-row (tid&1): 4 cpa16
    int arow = tid >> 1;
    int ahal = tid & 1;
    const __half* aSrc;
    if (MODE == 1) {
        int mc = (arow < valid) ? arow : (valid - 1);
        aSrc = A + (size_t)g_perm[row0 + mc] * Kd;
    } else {
        aSrc = A + (size_t)(row0 + arow) * Kd;
    }
    // B: thread covers row tid: 8 cpa16
    const __half* bSrc = Bp + (size_t)(col0 + tid) * Kd;

    auto load_stage = [&](int kt, int buf) {   // kt in halves
        uint32_t aB = sb + SM_A + buf * A_STAGE + arow * ROWB + ahal * 64;
        uint32_t bB = sb + SM_B + buf * B_STAGE + tid * ROWB;
        const __half* ap = aSrc + kt + ahal * 32;
        const __half* bpS = bSrc + kt;
        #pragma unroll
        for (int i = 0; i < 4; i++) cpa16(aB + i * 16, ap + i * 8);
        #pragma unroll
        for (int i = 0; i < 8; i++) cpa16(bB + i * 16, bpS + i * 8);
        CP_COMMIT();
    };

    // ---- per-lane ldmatrix base offsets (within a stage buffer) ----
    // A (per mi): rows warpM*64 + mi*16 + (lane&15), koff (lane>>4)*16
    uint32_t aLdsmOff[4];
    #pragma unroll
    for (int mi = 0; mi < 4; mi++)
        aLdsmOff[mi] = (uint32_t)(warpM * 64 + mi * 16 + (lane & 15)) * ROWB + (lane >> 4) * 16;
    // B (per nj-pair p): rows warpN*64 + p*16 + (lane>>4)*8 + (lane&7), koff ((lane>>3)&1)*16
    uint32_t bLdsmOff[4];
    #pragma unroll
    for (int p = 0; p < 4; p++)
        bLdsmOff[p] = (uint32_t)(warpN * 64 + p * 16 + ((lane >> 4) << 3) + (lane & 7)) * ROWB
                    + ((lane >> 3) & 1) * 16;

    float acc[4][8][4];
    #pragma unroll
    for (int mi = 0; mi < 4; mi++)
        #pragma unroll
        for (int nj = 0; nj < 8; nj++)
            #pragma unroll
            for (int q = 0; q < 4; q++) acc[mi][nj][q] = 0.f;

    int NK = Kd >> 6;   // stages of 64 halves
    load_stage(0, 0);

    for (int kt = 0; kt < NK; kt++) {
        int buf = kt & 1;
        if (kt + 1 < NK) load_stage((kt + 1) << 6, (kt + 1) & 1);
        else CP_COMMIT();
        CP_WAIT1();
        __syncthreads();

        uint32_t aBase = sb + SM_A + buf * A_STAGE;
        uint32_t bBase = sb + SM_B + buf * B_STAGE;
        #pragma unroll
        for (int k16 = 0; k16 < 4; k16++) {
            uint32_t kb = k16 * 32;
            uint32_t af[4][4], bf[8][2];
            #pragma unroll
            for (int mi = 0; mi < 4; mi++)
                LDSM_X4(af[mi][0], af[mi][1], af[mi][2], af[mi][3], aBase + aLdsmOff[mi] + kb);
            #pragma unroll
            for (int p = 0; p < 4; p++)
                LDSM_X4(bf[2 * p][0], bf[2 * p][1], bf[2 * p + 1][0], bf[2 * p + 1][1],
                        bBase + bLdsmOff[p] + kb);
            #pragma unroll
            for (int mi = 0; mi < 4; mi++)
                #pragma unroll
                for (int nj = 0; nj < 8; nj++)
                    MMA_F16(acc[mi][nj], af[mi], bf[nj]);
        }
        __syncthreads();
    }

    // ---- epilogue ----
    #pragma unroll
    for (int mi = 0; mi < 4; mi++) {
        int li0 = warpM * 64 + mi * 16 + gid;
        int li1 = li0 + 8;
        bool ok0 = (MODE == 0) || (li0 < valid);
        bool ok1 = (MODE == 0) || (li1 < valid);
        #pragma unroll
        for (int nj = 0; nj < 8; nj++) {
            int c = warpN * 64 + nj * 8 + tig * 2;
            float b0 = bp[col0 + c], b1 = bp[col0 + c + 1];
            float v0 = acc[mi][nj][0] + b0;
            float v1 = acc[mi][nj][1] + b1;
            float v2 = acc[mi][nj][2] + b0;
            float v3 = acc[mi][nj][3] + b1;
            if (GELU) {
                v0 = gelu_exact(v0); v1 = gelu_exact(v1);
                v2 = gelu_exact(v2); v3 = gelu_exact(v3);
            }
            if (OUTH) {
                __half* C = (__half*)Cv;
                if (ok0) *(__half2*)(C + (size_t)(row0 + li0) * N + col0 + c) = __floats2half2_rn(v0, v1);
                if (ok1) *(__half2*)(C + (size_t)(row0 + li1) * N + col0 + c) = __floats2half2_rn(v2, v3);
            } else {
                float* C = (float*)Cv;
                if (ok0) *(float2*)(C + (size_t)(row0 + li0) * N + col0 + c) = make_float2(v0, v1);
                if (ok1) *(float2*)(C + (size_t)(row0 + li1) * N + col0 + c) = make_float2(v2, v3);
            }
        }
    }
}

// ---------------- combine + LN2 ----------------
__global__ void combine_kernel(const float* __restrict__ g2,
                               const float* __restrict__ b2,
                               float* __restrict__ out) {
    int t = blockIdx.x, tid = threadIdx.x;
    int r0 = g_rank[2 * t], r1 = g_rank[2 * t + 1];
    float w0 = g_tkw[2 * t], w1 = g_tkw[2 * t + 1];
    const float* sh = g_sh + (size_t)t * OO;
    const float* e0 = g_eout2 + (size_t)r0 * OO;
    const float* e1 = g_eout2 + (size_t)r1 * OO;
    float v[4], s = 0.f, s2 = 0.f;
    #pragma unroll
    for (int i = 0; i < 4; i++) {
        int o = tid + i * 256;
        v[i] = sh[o] * (1.0f / 9.0f) + w0 * e0[o] + w1 * e1[o];
        s += v[i]; s2 += v[i] * v[i];
    }
    __shared__ float shm[16];
    block_reduce2(s, s2, shm);
    float m   = s  * (1.0f / OO);
    float var = s2 * (1.0f / OO) - m * m;
    float inv = rsqrtf(var + 1e-5f);
    float* orow = out + (size_t)t * OO;
    #pragma unroll
    for (int i = 0; i < 4; i++) {
        int o = tid + i * 256;
        orow[o] = (v[i] - m) * inv * g2[o] + b2[o];
    }
}

// ---------------- launch ----------------
extern "C" void kernel_launch(void* const* d_in, const int* in_sizes, int n_in,
                              void* d_out, int out_size) {
    const float* x        = (const float*)d_in[0];
    const float* ln1_g    = (const float*)d_in[1];
    const float* ln1_b    = (const float*)d_in[2];
    const float* router_w = (const float*)d_in[3];
    const float* router_b = (const float*)d_in[4];
    const float* sh_w1    = (const float*)d_in[5];
    const float* sh_b1    = (const float*)d_in[6];
    const float* sh_w2    = (const float*)d_in[7];
    const float* sh_b2    = (const float*)d_in[8];
    const float* e_w1     = (const float*)d_in[9];
    const float* e_b1     = (const float*)d_in[10];
    const float* e_w2     = (const float*)d_in[11];
    const float* e_b2     = (const float*)d_in[12];
    const float* ln2_g    = (const float*)d_in[13];
    const float* ln2_b    = (const float*)d_in[14];
    float* out = (float*)d_out;

    __half *p_xh, *p_h1h, *p_hid2h, *p_w1h, *p_w2h, *p_sw1h, *p_sw2h;
    float *p_sh, *p_eout2;
    cudaGetSymbolAddress((void**)&p_xh,    g_xh);
    cudaGetSymbolAddress((void**)&p_h1h,   g_h1h);
    cudaGetSymbolAddress((void**)&p_sh,    g_sh);
    cudaGetSymbolAddress((void**)&p_hid2h, g_hid2h);
    cudaGetSymbolAddress((void**)&p_eout2, g_eout2);
    cudaGetSymbolAddress((void**)&p_w1h,   g_w1h);
    cudaGetSymbolAddress((void**)&p_w2h,   g_w2h);
    cudaGetSymbolAddress((void**)&p_sw1h,  g_sw1h);
    cudaGetSymbolAddress((void**)&p_sw2h,  g_sw2h);

    cudaFuncSetAttribute(mma_gemm<0, true , true >, cudaFuncAttributeMaxDynamicSharedMemorySize, GEMM_SMEM);
    cudaFuncSetAttribute(mma_gemm<0, false, false>, cudaFuncAttributeMaxDynamicSharedMemorySize, GEMM_SMEM);
    cudaFuncSetAttribute(mma_gemm<1, true , true >, cudaFuncAttributeMaxDynamicSharedMemorySize, GEMM_SMEM);
    cudaFuncSetAttribute(mma_gemm<2, false, false>, cudaFuncAttributeMaxDynamicSharedMemorySize, GEMM_SMEM);

    // all weights fp32 -> fp16 in one pass (also resets counts)
    cvt_all_kernel<<<(N8_ALL + 255) / 256, 256>>>((const float4*)e_w1, (const float4*)e_w2,
                                                  (const float4*)sh_w1, (const float4*)sh_w2);

    ln1_router_kernel<<<TT, 256>>>(x, ln1_g, ln1_b, router_w, router_b);
    prefix_kernel<<<1, 1>>>();
    place_kernel<<<(TT * 2) / 256, 256>>>();

    // shared GEMM1 (GELU, half out): [T,H] = xh @ sw1^T
    mma_gemm<0, true , true ><<<dim3(HH / 256, TT / 128), 256, GEMM_SMEM>>>(p_xh, p_sw1h, sh_b1, p_h1h, HH, DD);
    // shared GEMM2 (fp32 out): [T,O] = h1 @ sw2^T
    mma_gemm<0, false, false><<<dim3(OO / 256, TT / 128), 256, GEMM_SMEM>>>(p_h1h, p_sw2h, sh_b2, p_sh, OO, HH);
    // expert GEMM1 (gathered, GELU, half out): hid2 = xh[perm] @ w1h[e]^T
    mma_gemm<1, true , true ><<<dim3(HH / 256, MAXTILES), 256, GEMM_SMEM>>>(p_xh, p_w1h, e_b1, p_hid2h, HH, DD);
    // expert GEMM2 (fp32 out): eout2 = hid2 @ w2h[e]^T
    mma_gemm<2, false, false><<<dim3(OO / 256, MAXTILES), 256, GEMM_SMEM>>>(p_hid2h, p_w2h, e_b2, p_eout2, OO, HH);

    combine_kernel<<<TT, 256>>>(ln2_g, ln2_b, out);
}

// round 9
// speedup vs baseline: 6.0028x; 1.3910x over previous
#include <cuda_runtime.h>
#include <cuda_fp16.h>
#include <math.h>
#include <stdint.h>

// ---------------- compile-time problem shape ----------------
#define TT 4096    // B*S tokens
#define DD 1024
#define HH 2048
#define OO 1024
#define EE 8
#define NSHTILES (TT/128)                 // 32 shared-expert tiles
#define MAXTILES (71 + NSHTILES + 1)      // expert tiles (<=71) + shared + pad
#define BUFROWS (MAXTILES*128)

// ---------------- scratch (device globals) ----------------
__device__ __half g_xh   [(size_t)TT*DD];        // LN1 output (fp16)
__device__ __half g_hid2h[(size_t)BUFROWS*HH];   // hidden, compact (fp16)
__device__ float  g_eout2[(size_t)BUFROWS*OO];   // output, compact (fp32)
__device__ __half g_w1h [(size_t)EE*HH*DD];
__device__ __half g_w2h [(size_t)EE*OO*HH];
__device__ __half g_sw1h[(size_t)HH*DD];
__device__ __half g_sw2h[(size_t)OO*HH];

__device__ int   g_tki [TT*2];
__device__ float g_tkw [TT*2];
__device__ int   g_rank[TT*2];
__device__ int   g_perm[BUFROWS];
__device__ int   g_counts[EE];
__device__ int   g_cursor[EE];
__device__ int   g_base[EE];
__device__ int   g_sbase;                        // row base of shared-expert segment
__device__ int   g_tile_expert[MAXTILES];
__device__ int   g_tile_rows[MAXTILES];

// ---------------- PTX helpers (baseline features; legal on compute_103) ----------------
__device__ __forceinline__ uint32_t smem_u32(const void* p) {
    uint32_t a;
    asm("{ .reg .u64 t; cvta.to.shared.u64 t, %1; cvt.u32.u64 %0, t; }" : "=r"(a) : "l"(p));
    return a;
}
__device__ __forceinline__ void cpa16(uint32_t dst, const void* src) {
    asm volatile("cp.async.cg.shared.global [%0], [%1], 16;" :: "r"(dst), "l"(src));
}
#define CP_COMMIT() asm volatile("cp.async.commit_group;" ::: "memory")
#define CP_WAIT0()  asm volatile("cp.async.wait_group 0;" ::: "memory")
#define CP_WAIT1()  asm volatile("cp.async.wait_group 1;" ::: "memory")
#define CP_WAIT2()  asm volatile("cp.async.wait_group 2;" ::: "memory")

#define MMA_F16(c, a, b) \
    asm volatile("mma.sync.aligned.m16n8k16.row.col.f32.f16.f16.f32 " \
        "{%0,%1,%2,%3}, {%4,%5,%6,%7}, {%8,%9}, {%0,%1,%2,%3};" \
        : "+f"((c)[0]), "+f"((c)[1]), "+f"((c)[2]), "+f"((c)[3]) \
        : "r"((a)[0]), "r"((a)[1]), "r"((a)[2]), "r"((a)[3]), \
          "r"((b)[0]), "r"((b)[1]))

#define LDSM_X4(r0, r1, r2, r3, addr) \
    asm volatile("ldmatrix.sync.aligned.m8n8.x4.shared.b16 {%0,%1,%2,%3}, [%4];" \
        : "=r"(r0), "=r"(r1), "=r"(r2), "=r"(r3) : "r"(addr))

__device__ __forceinline__ float gelu_exact(float x) {
    return 0.5f * x * (1.0f + erff(x * 0.70710678118654752440f));
}

__device__ __forceinline__ void block_reduce2(float& s, float& s2, float* sh) {
    #pragma unroll
    for (int o = 16; o; o >>= 1) {
        s  += __shfl_down_sync(0xffffffffu, s,  o);
        s2 += __shfl_down_sync(0xffffffffu, s2, o);
    }
    int w = threadIdx.x >> 5, l = threadIdx.x & 31;
    if (l == 0) { sh[w] = s; sh[8 + w] = s2; }
    __syncthreads();
    if (threadIdx.x == 0) {
        float a = 0.f, b = 0.f;
        #pragma unroll
        for (int i = 0; i < 8; i++) { a += sh[i]; b += sh[8 + i]; }
        sh[0] = a; sh[8] = b;
    }
    __syncthreads();
    s = sh[0]; s2 = sh[8];
}

// ---------------- fused fp32->fp16 convert of ALL weights (+ counter reset) ----------------
#define N8_EW1 (EE*HH*DD/8)
#define N8_EW2 (EE*OO*HH/8)
#define N8_SW1 (HH*DD/8)
#define N8_SW2 (OO*HH/8)
#define N8_ALL (N8_EW1 + N8_EW2 + N8_SW1 + N8_SW2)

__global__ void cvt_all_kernel(const float4* __restrict__ ew1, const float4* __restrict__ ew2,
                               const float4* __restrict__ sw1, const float4* __restrict__ sw2) {
    if (blockIdx.x == 0 && threadIdx.x < EE) g_counts[threadIdx.x] = 0;
    int i = blockIdx.x * blockDim.x + threadIdx.x;
    if (i >= N8_ALL) return;
    const float4* src; uint4* dst; int j = i;
    if (j < N8_EW1)                 { src = ew1; dst = (uint4*)g_w1h; }
    else if ((j -= N8_EW1) < N8_EW2){ src = ew2; dst = (uint4*)g_w2h; }
    else if ((j -= N8_EW2) < N8_SW1){ src = sw1; dst = (uint4*)g_sw1h; }
    else { j -= N8_SW1;               src = sw2; dst = (uint4*)g_sw2h; }
    float4 v0 = src[2 * j], v1 = src[2 * j + 1];
    __half2 h0 = __floats2half2_rn(v0.x, v0.y);
    __half2 h1 = __floats2half2_rn(v0.z, v0.w);
    __half2 h2 = __floats2half2_rn(v1.x, v1.y);
    __half2 h3 = __floats2half2_rn(v1.z, v1.w);
    uint4 w;
    w.x = *(uint32_t*)&h0; w.y = *(uint32_t*)&h1;
    w.z = *(uint32_t*)&h2; w.w = *(uint32_t*)&h3;
    dst[j] = w;
}

// ---------------- fused LN1 + router (one block / token) ----------------
__global__ void ln1_router_kernel(const float* __restrict__ x,
                                  const float* __restrict__ g,
                                  const float* __restrict__ b,
                                  const float* __restrict__ rw,
                                  const float* __restrict__ rb) {
    int t = blockIdx.x, tid = threadIdx.x;
    const float* xr = x + (size_t)t * DD;
    float v[4], s = 0.f, s2 = 0.f;
    #pragma unroll
    for (int i = 0; i < 4; i++) {
        v[i] = xr[tid + i * 256];
        s += v[i]; s2 += v[i] * v[i];
    }
    __shared__ float sh[16];
    block_reduce2(s, s2, sh);
    float m   = s  * (1.0f / DD);
    float var = s2 * (1.0f / DD) - m * m;
    float inv = rsqrtf(var + 1e-5f);

    __half* yr = g_xh + (size_t)t * DD;
    float p[EE];
    #pragma unroll
    for (int e = 0; e < EE; e++) p[e] = 0.f;
    #pragma unroll
    for (int i = 0; i < 4; i++) {
        int d = tid + i * 256;
        float y = (v[i] - m) * inv * g[d] + b[d];
        yr[d] = __float2half_rn(y);
        #pragma unroll
        for (int e = 0; e < EE; e++) p[e] += y * rw[e * DD + d];
    }
    __shared__ float sl[256][EE];
    #pragma unroll
    for (int e = 0; e < EE; e++) sl[tid][e] = p[e];
    __syncthreads();
    for (int o = 128; o; o >>= 1) {
        if (tid < o) {
            #pragma unroll
            for (int e = 0; e < EE; e++) sl[tid][e] += sl[tid + o][e];
        }
        __syncthreads();
    }
    if (tid == 0) {
        float l[EE];
        #pragma unroll
        for (int e = 0; e < EE; e++) l[e] = sl[0][e] + rb[e];
        int i0 = 0;
        #pragma unroll
        for (int e = 1; e < EE; e++) if (l[e] > l[i0]) i0 = e;
        int i1 = (i0 == 0) ? 1 : 0;
        #pragma unroll
        for (int e = 0; e < EE; e++) if (e != i0 && l[e] > l[i1]) i1 = e;
        float e1 = expf(l[i1] - l[i0]);
        float invp = 1.0f / (1.0f + e1);
        g_tki[2 * t] = i0;  g_tki[2 * t + 1] = i1;
        g_tkw[2 * t] = invp; g_tkw[2 * t + 1] = e1 * invp;
        atomicAdd(&g_counts[i0], 1);
        atomicAdd(&g_counts[i1], 1);
    }
}

// ---------------- segment prefix (experts, then shared-expert segment) ----------------
__global__ void prefix_kernel() {
    int rowbase = 0, tile = 0;
    for (int e = 0; e < EE; e++) {
        int cnt = g_counts[e];
        g_base[e] = rowbase;
        g_cursor[e] = 0;
        int nt = (cnt + 127) >> 7;
        for (int j = 0; j < nt; j++) {
            g_tile_expert[tile] = e;
            int rem = cnt - j * 128;
            g_tile_rows[tile] = rem < 128 ? rem : 128;
            tile++;
        }
        rowbase += nt << 7;
    }
    g_sbase = rowbase;
    for (int j = 0; j < NSHTILES; j++) {
        g_tile_expert[tile] = EE;   // shared expert id
        g_tile_rows[tile] = 128;
        tile++;
    }
    for (; tile < MAXTILES; tile++) { g_tile_expert[tile] = -1; g_tile_rows[tile] = 0; }
}

// ---------------- placement (experts + identity perm for shared segment) ----------------
__global__ void place_kernel() {
    int i = blockIdx.x * blockDim.x + threadIdx.x;
    if (i < TT * 2) {
        int e = g_tki[i];
        int pos = g_base[e] + atomicAdd(&g_cursor[e], 1);
        g_perm[pos] = i >> 1;
        g_rank[i] = pos;
    } else if (i < TT * 3) {
        int t = i - TT * 2;
        g_perm[g_sbase + t] = t;
    }
}

// ============ fp16 mma.sync GEMM: C[M,N] = A[M,K] @ W[e][N,K]^T + bias ============
// BM=128, BN=256, BK=32 halves, 4-stage cp.async, 512 threads = 16 warps (2M x 8N),
// warp tile 64x32. Rows padded to 80B (conflict-free LDSM phases).
// WHICH 1: A gathered via g_perm, W = w1/sw1, GELU, fp16 out.
// WHICH 2: A compact rows direct, W = w2/sw2, fp32 out.
#define ROWB 80
#define A_BYTES (128 * ROWB)              // 10240
#define B_BYTES (256 * ROWB)              // 20480
#define STAGE   (A_BYTES + B_BYTES)       // 30720
#define NSTG 4
#define GEMM_SMEM (NSTG * STAGE)          // 122880

template <int WHICH>
__global__ __launch_bounds__(512, 1)
void moe_gemm(const __half* __restrict__ A,
              const __half* __restrict__ Wexp, const __half* __restrict__ Wsh,
              const float* __restrict__ bexp, const float* __restrict__ bsh,
              void* __restrict__ Cv, int N, int Kd) {
    int tileM = blockIdx.y, tileN = blockIdx.x;
    int e = g_tile_expert[tileM];
    if (e < 0) return;
    int valid = g_tile_rows[tileM];
    const __half* Bp;
    const float* bp;
    if (e < EE) {
        Bp = Wexp + (size_t)e * ((size_t)N * Kd);
        bp = bexp + (size_t)e * N;
    } else {
        Bp = Wsh;
        bp = bsh;
    }
    int row0 = tileM * 128, col0 = tileN * 256;
    int tid = threadIdx.x;
    int wid = tid >> 5, lane = tid & 31;
    int gid = lane >> 2, tig = lane & 3;
    int warpM = wid & 1, warpN = wid >> 1;   // 2 x 8

    extern __shared__ char smem[];
    uint32_t sb = smem_u32(smem);

    // ---- loaders: A 512 cpa16 (1/thread), B 1024 cpa16 (2/thread) ----
    int arow = tid >> 2, achk = tid & 3;
    const __half* aSrc;
    if (WHICH == 1) {
        int mc = (arow < valid) ? arow : (valid - 1);
        aSrc = A + (size_t)g_perm[row0 + mc] * Kd + achk * 8;
    } else {
        aSrc = A + (size_t)(row0 + arow) * Kd + achk * 8;
    }
    const __half* b0Src = Bp + (size_t)(col0 + arow) * Kd + achk * 8;
    const __half* b1Src = Bp + (size_t)(col0 + 128 + arow) * Kd + achk * 8;
    uint32_t aDst  = sb + arow * ROWB + achk * 16;
    uint32_t b0Dst = sb + A_BYTES + arow * ROWB + achk * 16;
    uint32_t b1Dst = sb + A_BYTES + (128 + arow) * ROWB + achk * 16;

    auto load_stage = [&](int kt, int s) {   // kt in halves
        uint32_t off = s * STAGE;
        cpa16(aDst + off,  aSrc + kt);
        cpa16(b0Dst + off, b0Src + kt);
        cpa16(b1Dst + off, b1Src + kt);
        CP_COMMIT();
    };

    // ---- ldmatrix lane offsets ----
    uint32_t aOff[4];
    #pragma unroll
    for (int mi = 0; mi < 4; mi++)
        aOff[mi] = (uint32_t)(warpM * 64 + mi * 16 + (lane & 15)) * ROWB + (lane >> 4) * 16;
    uint32_t bOff[2];
    #pragma unroll
    for (int p = 0; p < 2; p++)
        bOff[p] = (uint32_t)A_BYTES
                + (uint32_t)(warpN * 32 + p * 16 + ((lane >> 4) << 3) + (lane & 7)) * ROWB
                + ((lane >> 3) & 1) * 16;

    float acc[4][4][4];
    #pragma unroll
    for (int mi = 0; mi < 4; mi++)
        #pragma unroll
        for (int nj = 0; nj < 4; nj++)
            #pragma unroll
            for (int q = 0; q < 4; q++) acc[mi][nj][q] = 0.f;

    int NK = Kd >> 5;   // stages of 32 halves
    load_stage(0, 0);
    load_stage(32, 1);
    load_stage(64, 2);
    CP_WAIT2();
    __syncthreads();

    for (int kt = 0; kt < NK; kt++) {
        uint32_t base = sb + (kt & 3) * STAGE;
        #pragma unroll
        for (int k16 = 0; k16 < 2; k16++) {
            uint32_t kb = k16 * 32;
            uint32_t af[4][4], bf[4][2];
            #pragma unroll
            for (int mi = 0; mi < 4; mi++)
                LDSM_X4(af[mi][0], af[mi][1], af[mi][2], af[mi][3], base + aOff[mi] + kb);
            #pragma unroll
            for (int p = 0; p < 2; p++)
                LDSM_X4(bf[2 * p][0], bf[2 * p][1], bf[2 * p + 1][0], bf[2 * p + 1][1],
                        base + bOff[p] + kb);
            #pragma unroll
            for (int mi = 0; mi < 4; mi++)
                #pragma unroll
                for (int nj = 0; nj < 4; nj++)
                    MMA_F16(acc[mi][nj], af[mi], bf[nj]);
        }
        if (kt + 3 < NK) load_stage((kt + 3) << 5, (kt + 3) & 3);
        if (kt + 1 < NK) {
            if (kt + 3 < NK)      CP_WAIT2();
            else if (kt + 2 < NK) CP_WAIT1();
            else                  CP_WAIT0();
            __syncthreads();
        }
    }

    // ---- epilogue ----
    #pragma unroll
    for (int mi = 0; mi < 4; mi++) {
        int li0 = warpM * 64 + mi * 16 + gid;
        int li1 = li0 + 8;
        bool ok0 = li0 < valid;
        bool ok1 = li1 < valid;
        #pragma unroll
        for (int nj = 0; nj < 4; nj++) {
            int c = warpN * 32 + nj * 8 + tig * 2;
            float b0 = bp[col0 + c], b1 = bp[col0 + c + 1];
            float v0 = acc[mi][nj][0] + b0;
            float v1 = acc[mi][nj][1] + b1;
            float v2 = acc[mi][nj][2] + b0;
            float v3 = acc[mi][nj][3] + b1;
            if (WHICH == 1) {
                v0 = gelu_exact(v0); v1 = gelu_exact(v1);
                v2 = gelu_exact(v2); v3 = gelu_exact(v3);
                __half* C = (__half*)Cv;
                if (ok0) *(__half2*)(C + (size_t)(row0 + li0) * N + col0 + c) = __floats2half2_rn(v0, v1);
                if (ok1) *(__half2*)(C + (size_t)(row0 + li1) * N + col0 + c) = __floats2half2_rn(v2, v3);
            } else {
                float* C = (float*)Cv;
                if (ok0) *(float2*)(C + (size_t)(row0 + li0) * N + col0 + c) = make_float2(v0, v1);
                if (ok1) *(float2*)(C + (size_t)(row0 + li1) * N + col0 + c) = make_float2(v2, v3);
            }
        }
    }
}

// ---------------- combine (shared/9 + top-2 mix) + LN2 ----------------
__global__ void combine_kernel(const float* __restrict__ g2,
                               const float* __restrict__ b2,
                               float* __restrict__ out) {
    int t = blockIdx.x, tid = threadIdx.x;
    int r0 = g_rank[2 * t], r1 = g_rank[2 * t + 1];
    float w0 = g_tkw[2 * t], w1 = g_tkw[2 * t + 1];
    const float* sh = g_eout2 + (size_t)(g_sbase + t) * OO;
    const float* e0 = g_eout2 + (size_t)r0 * OO;
    const float* e1 = g_eout2 + (size_t)r1 * OO;
    float v[4], s = 0.f, s2 = 0.f;
    #pragma unroll
    for (int i = 0; i < 4; i++) {
        int o = tid + i * 256;
        v[i] = sh[o] * (1.0f / 9.0f) + w0 * e0[o] + w1 * e1[o];
        s += v[i]; s2 += v[i] * v[i];
    }
    __shared__ float shm[16];
    block_reduce2(s, s2, shm);
    float m   = s  * (1.0f / OO);
    float var = s2 * (1.0f / OO) - m * m;
    float inv = rsqrtf(var + 1e-5f);
    float* orow = out + (size_t)t * OO;
    #pragma unroll
    for (int i = 0; i < 4; i++) {
        int o = tid + i * 256;
        orow[o] = (v[i] - m) * inv * g2[o] + b2[o];
    }
}

// ---------------- launch ----------------
extern "C" void kernel_launch(void* const* d_in, const int* in_sizes, int n_in,
                              void* d_out, int out_size) {
    const float* x        = (const float*)d_in[0];
    const float* ln1_g    = (const float*)d_in[1];
    const float* ln1_b    = (const float*)d_in[2];
    const float* router_w = (const float*)d_in[3];
    const float* router_b = (const float*)d_in[4];
    const float* sh_w1    = (const float*)d_in[5];
    const float* sh_b1    = (const float*)d_in[6];
    const float* sh_w2    = (const float*)d_in[7];
    const float* sh_b2    = (const float*)d_in[8];
    const float* e_w1     = (const float*)d_in[9];
    const float* e_b1     = (const float*)d_in[10];
    const float* e_w2     = (const float*)d_in[11];
    const float* e_b2     = (const float*)d_in[12];
    const float* ln2_g    = (const float*)d_in[13];
    const float* ln2_b    = (const float*)d_in[14];
    float* out = (float*)d_out;

    __half *p_xh, *p_hid2h, *p_w1h, *p_w2h, *p_sw1h, *p_sw2h;
    float *p_eout2;
    cudaGetSymbolAddress((void**)&p_xh,    g_xh);
    cudaGetSymbolAddress((void**)&p_hid2h, g_hid2h);
    cudaGetSymbolAddress((void**)&p_eout2, g_eout2);
    cudaGetSymbolAddress((void**)&p_w1h,   g_w1h);
    cudaGetSymbolAddress((void**)&p_w2h,   g_w2h);
    cudaGetSymbolAddress((void**)&p_sw1h,  g_sw1h);
    cudaGetSymbolAddress((void**)&p_sw2h,  g_sw2h);

    cudaFuncSetAttribute(moe_gemm<1>, cudaFuncAttributeMaxDynamicSharedMemorySize, GEMM_SMEM);
    cudaFuncSetAttribute(moe_gemm<2>, cudaFuncAttributeMaxDynamicSharedMemorySize, GEMM_SMEM);

    // all weights fp32 -> fp16 in one pass (also resets counts)
    cvt_all_kernel<<<(N8_ALL + 255) / 256, 256>>>((const float4*)e_w1, (const float4*)e_w2,
                                                  (const float4*)sh_w1, (const float4*)sh_w2);

    ln1_router_kernel<<<TT, 256>>>(x, ln1_g, ln1_b, router_w, router_b);
    prefix_kernel<<<1, 1>>>();
    place_kernel<<<(TT * 3) / 256, 256>>>();

    // GEMM1 (gather + GELU, fp16 out): hid = gelu(x[perm] @ w1[e]^T + b1[e])
    moe_gemm<1><<<dim3(HH / 256, MAXTILES), 512, GEMM_SMEM>>>(
        p_xh, p_w1h, p_sw1h, e_b1, sh_b1, p_hid2h, HH, DD);
    // GEMM2 (compact rows, fp32 out): eout = hid @ w2[e]^T + b2[e]
    moe_gemm<2><<<dim3(OO / 256, MAXTILES), 512, GEMM_SMEM>>>(
        p_hid2h, p_w2h, p_sw2h, e_b2, sh_b2, p_eout2, OO, HH);

    combine_kernel<<<TT, 256>>>(ln2_g, ln2_b, out);
}